// round 1
// baseline (speedup 1.0000x reference)
#include <cuda_runtime.h>
#include <math.h>

#define TE 128
#define THREADS 512
#define SMEM_FLOATS 47616
#define SMEM_BYTES (SMEM_FLOATS * 4)

__device__ __forceinline__ float swishf(float x) {
    return x * (1.0f / (1.0f + __expf(-x)));
}

extern "C" __global__ void __launch_bounds__(THREADS, 1)
mp_kernel(const float* __restrict__ vectors,
          const float* __restrict__ node_s,
          const float* __restrict__ node_v,
          const float* __restrict__ W0,
          const float* __restrict__ W1,
          const float* __restrict__ W2,
          const int* __restrict__ senders,
          const int* __restrict__ receivers,
          float* __restrict__ out,
          int E, int numTiles)
{
    extern __shared__ float sm[];
    float* W0s  = sm;            // [8][64]      512
    float* W1s  = sm + 512;      // [64][64]     4096
    float* W2s  = sm + 4608;     // [64][128]    8192 (112 cols + zero pad)
    float* us   = sm + 12800;    // [128][4]     512
    float* embT = sm + 13312;    // [8][128]     1024
    float* h1T  = sm + 14336;    // [64][128]    8192
    float* h2T  = sm + 22528;    // [64][128]    8192
    float* svs  = sm + 13312;    // [128][84]    10752 (aliases embT/h1T, dead then)
    float* dots = sm + 24064;    // [128][16]    2048  (aliases h2T tail, dead then)
    float* mixs = sm + 30720;    // [128][132]   16896

    const int t = threadIdx.x;

    // ---- load weights once per block, fold all scale factors ----
    for (int i = t; i < 512; i += THREADS)  W0s[i] = W0[i] * 0.35355339059327373f;  // 1/sqrt(8)
    for (int i = t; i < 4096; i += THREADS) W1s[i] = W1[i] * 0.125f;                // 1/sqrt(64)
    for (int i = t; i < 8192; i += THREADS) {
        int k = i >> 7, c = i & 127;
        float scl = 0.03125f;                       // 1/sqrt(64) * 1/sqrt(16)
        if (c >= 96) scl *= 1.224744871391589f;     // sqrt(1.5) folded for path_c gates
        W2s[i] = (c < 112) ? W2[k * 112 + c] * scl : 0.0f;
    }
    __syncthreads();

    for (int tile = blockIdx.x; tile < numTiles; tile += gridDim.x) {
        const int e0 = tile * TE;

        // ---- stage 1: geometry + radial (Bessel * envelope) embedding ----
        if (t < TE) {
            int e = e0 + t;
            float vx = 0.f, vy = 0.f, vz = 0.f;
            if (e < E) { vx = vectors[3*e+0]; vy = vectors[3*e+1]; vz = vectors[3*e+2]; }
            float r = sqrtf(vx*vx + vy*vy + vz*vz);
            float rinv = (r > 1e-12f) ? 1.0f / r : 0.0f;
            us[4*t+0] = vx*rinv; us[4*t+1] = vy*rinv; us[4*t+2] = vz*rinv; us[4*t+3] = 0.f;
            float env = 0.0f;
            if (r < 1.0f) {
                float x2 = r*r, x4 = x2*x2, x6 = x4*x2, x7 = x6*r, x8 = x4*x4;
                env = 1.0f - 28.0f*x6 + 48.0f*x7 - 21.0f*x8;
            }
            float pref = (r > 0.0f) ? 1.4142135623730951f * rinv * env : 0.0f;
            float s1, c1;
            sincosf(3.14159265358979323846f * r, &s1, &c1);
            // sin(n*theta) Chebyshev recurrence
            float sn = s1, sp = 0.0f, c2 = 2.0f * c1;
            #pragma unroll
            for (int n = 0; n < 8; n++) {
                embT[n*TE + t] = pref * sn;
                float nx = c2 * sn - sp;
                sp = sn; sn = nx;
            }
        }
        __syncthreads();

        // ---- GEMM1: h1T = swish(embT^T @ W0s), [128 e][64 c] ----
        {
            int eg = (t & 31) * 4;
            int cg = (t >> 5) * 4;
            float acc[4][4];
            #pragma unroll
            for (int a = 0; a < 4; a++)
                #pragma unroll
                for (int b = 0; b < 4; b++) acc[a][b] = 0.f;
            #pragma unroll
            for (int k = 0; k < 8; k++) {
                float4 a = *(const float4*)(embT + k*TE + eg);
                float4 b = *(const float4*)(W0s + k*64 + cg);
                acc[0][0] += a.x*b.x; acc[0][1] += a.x*b.y; acc[0][2] += a.x*b.z; acc[0][3] += a.x*b.w;
                acc[1][0] += a.y*b.x; acc[1][1] += a.y*b.y; acc[1][2] += a.y*b.z; acc[1][3] += a.y*b.w;
                acc[2][0] += a.z*b.x; acc[2][1] += a.z*b.y; acc[2][2] += a.z*b.z; acc[2][3] += a.z*b.w;
                acc[3][0] += a.w*b.x; acc[3][1] += a.w*b.y; acc[3][2] += a.w*b.z; acc[3][3] += a.w*b.w;
            }
            #pragma unroll
            for (int c = 0; c < 4; c++) {
                float4 o;
                o.x = swishf(acc[0][c]); o.y = swishf(acc[1][c]);
                o.z = swishf(acc[2][c]); o.w = swishf(acc[3][c]);
                *(float4*)(h1T + (cg+c)*TE + eg) = o;
            }
        }
        __syncthreads();

        // ---- GEMM2: h2T = swish(h1T^T @ W1s) ----
        {
            int eg = (t & 31) * 4;
            int cg = (t >> 5) * 4;
            float acc[4][4];
            #pragma unroll
            for (int a = 0; a < 4; a++)
                #pragma unroll
                for (int b = 0; b < 4; b++) acc[a][b] = 0.f;
            #pragma unroll
            for (int k = 0; k < 64; k++) {
                float4 a = *(const float4*)(h1T + k*TE + eg);
                float4 b = *(const float4*)(W1s + k*64 + cg);
                acc[0][0] += a.x*b.x; acc[0][1] += a.x*b.y; acc[0][2] += a.x*b.z; acc[0][3] += a.x*b.w;
                acc[1][0] += a.y*b.x; acc[1][1] += a.y*b.y; acc[1][2] += a.y*b.z; acc[1][3] += a.y*b.w;
                acc[2][0] += a.z*b.x; acc[2][1] += a.z*b.y; acc[2][2] += a.z*b.z; acc[2][3] += a.z*b.w;
                acc[3][0] += a.w*b.x; acc[3][1] += a.w*b.y; acc[3][2] += a.w*b.z; acc[3][3] += a.w*b.w;
            }
            #pragma unroll
            for (int c = 0; c < 4; c++) {
                float4 o;
                o.x = swishf(acc[0][c]); o.y = swishf(acc[1][c]);
                o.z = swishf(acc[2][c]); o.w = swishf(acc[3][c]);
                *(float4*)(h2T + (cg+c)*TE + eg) = o;
            }
        }
        __syncthreads();

        // ---- GEMM3: mixs = h2T^T @ W2s  (row-major per edge, stride 132) ----
        {
            int eg = (t & 31) * 4;
            int cg = (t >> 5) * 8;
            float acc[4][8];
            #pragma unroll
            for (int a = 0; a < 4; a++)
                #pragma unroll
                for (int b = 0; b < 8; b++) acc[a][b] = 0.f;
            #pragma unroll 8
            for (int k = 0; k < 64; k++) {
                float4 a  = *(const float4*)(h2T + k*TE + eg);
                float4 b0 = *(const float4*)(W2s + k*128 + cg);
                float4 b1 = *(const float4*)(W2s + k*128 + cg + 4);
                float av[4] = {a.x, a.y, a.z, a.w};
                float bv[8] = {b0.x, b0.y, b0.z, b0.w, b1.x, b1.y, b1.z, b1.w};
                #pragma unroll
                for (int aa = 0; aa < 4; aa++)
                    #pragma unroll
                    for (int bb = 0; bb < 8; bb++)
                        acc[aa][bb] += av[aa] * bv[bb];
            }
            #pragma unroll
            for (int ee = 0; ee < 4; ee++) {
                float4 o0 = {acc[ee][0], acc[ee][1], acc[ee][2], acc[ee][3]};
                float4 o1 = {acc[ee][4], acc[ee][5], acc[ee][6], acc[ee][7]};
                float* row = mixs + (eg + ee) * 132 + cg;
                *(float4*)(row)     = o0;
                *(float4*)(row + 4) = o1;
            }
        }
        __syncthreads();

        // ---- message formation + vectorized atomic scatter (4 threads / edge) ----
        {
            int e   = t >> 2;
            int sub = t & 3;
            int eg  = e0 + e;
            bool ok = (eg < E);
            int snd = ok ? senders[eg] : 0;
            const float* sp = node_s + (size_t)snd * 32;
            const float* vp = node_v + (size_t)snd * 48;
            float* dst = svs + e * 84;     // s at [0..32), v flat at [32..80)

            #pragma unroll
            for (int q = 0; q < 5; q++) {
                int f4i = sub + 4*q;       // 0..19
                float4 val = {0.f, 0.f, 0.f, 0.f};
                if (ok) val = (f4i < 8) ? ((const float4*)sp)[f4i]
                                        : ((const float4*)vp)[f4i - 8];
                *(float4*)(dst + 4*f4i) = val;
            }
            __syncwarp();

            const float* usf = us + 4*e;
            float ux = usf[0], uy = usf[1], uz = usf[2];
            #pragma unroll
            for (int q = 0; q < 4; q++) {
                int c = 4*sub + q;
                const float* vv = dst + 32 + 3*c;
                dots[e*16 + c] = ux*vv[0] + uy*vv[1] + uz*vv[2];
            }
            __syncwarp();

            int rec = ok ? receivers[eg] : 0;
            float* obase = out + (size_t)rec * 240;
            const float* mx  = mixs + e * 132;
            const float* dts = dots + e * 16;

            #pragma unroll
            for (int it = 0; it < 15; it++) {
                int g = 4*it + sub;        // warp-uniform region per it (boundaries at 8,12,24,48)
                float4 val;
                if (g < 8) {               // msg_s: s * gate
                    float4 s4 = *(const float4*)(dst + 4*g);
                    float4 m4 = *(const float4*)(mx + 4*g);
                    val.x = s4.x*m4.x; val.y = s4.y*m4.y; val.z = s4.z*m4.z; val.w = s4.w*m4.w;
                } else if (g < 12) {       // msg_s: (v.u) * gate
                    float4 d4 = *(const float4*)(dts + (4*g - 32));
                    float4 m4 = *(const float4*)(mx + 4*g);
                    val.x = d4.x*m4.x; val.y = d4.y*m4.y; val.z = d4.z*m4.z; val.w = d4.w*m4.w;
                } else {                   // msg_v flat: [v | s*u | sqrt1.5*(u(u.v)-v/3)] * gate
                    int j0 = 4*g - 48;
                    float tmp[4];
                    #pragma unroll
                    for (int q2 = 0; q2 < 4; q2++) {
                        int j = j0 + q2;
                        int ch = j / 3;
                        int i  = j - 3*ch;
                        float m = mx[48 + ch];
                        float x;
                        if (ch < 16)      x = dst[32 + j];                       // v[ch][i]
                        else if (ch < 48) x = dst[ch - 16] * usf[i];             // s*u
                        else {
                            int c2 = ch - 48;
                            x = usf[i]*dts[c2] - dst[32 + 3*c2 + i] * 0.3333333333333333f;
                        }
                        tmp[q2] = x * m;
                    }
                    val.x = tmp[0]; val.y = tmp[1]; val.z = tmp[2]; val.w = tmp[3];
                }
                if (ok) {
                    float* addr = obase + 4*g;   // 16B aligned: 960*rec + 16*g
                    asm volatile("red.global.add.v4.f32 [%0], {%1,%2,%3,%4};"
                                 :: "l"(addr), "f"(val.x), "f"(val.y), "f"(val.z), "f"(val.w)
                                 : "memory");
                }
            }
        }
        __syncthreads();   // smem reused next tile
    }
}

extern "C" void kernel_launch(void* const* d_in, const int* in_sizes, int n_in,
                              void* d_out, int out_size) {
    const float* vectors   = (const float*)d_in[0];
    const float* node_s    = (const float*)d_in[1];
    const float* node_v    = (const float*)d_in[2];
    const float* W0        = (const float*)d_in[3];
    const float* W1        = (const float*)d_in[4];
    const float* W2        = (const float*)d_in[5];
    const int*   senders   = (const int*)d_in[6];
    const int*   receivers = (const int*)d_in[7];
    float*       out       = (float*)d_out;

    int E = in_sizes[6];
    int numTiles = (E + TE - 1) / TE;

    cudaFuncSetAttribute(mp_kernel, cudaFuncAttributeMaxDynamicSharedMemorySize, SMEM_BYTES);

    cudaMemsetAsync(d_out, 0, (size_t)out_size * sizeof(float), 0);

    int grid = 608;                 // ~4 waves of persistent tiles at 1 block/SM
    if (grid > numTiles) grid = numTiles;
    mp_kernel<<<grid, THREADS, SMEM_BYTES>>>(vectors, node_s, node_v, W0, W1, W2,
                                             senders, receivers, out, E, numTiles);
}

// round 3
// speedup vs baseline: 1.5106x; 1.5106x over previous
#include <cuda_runtime.h>
#include <cuda_bf16.h>
#include <math.h>
#include <stdint.h>

#define TE 128
#define THREADS 512

// ---- smem layout (32-bit word offsets) ----
// bf16 matrices use row stride 72 bf16 = 36 words (64 data + 8 pad)
#define ASTRIDE 36
#define OFF_W0    0        // fp32 [8][64] folded 1/sqrt(8)           512
#define OFF_B2H   512      // bf16 [64 n][72 k]  = W1^T/8 hi          2304
#define OFF_B2L   2816     //                          lo             2304
#define OFF_B3H   5120     // bf16 [112 n][72 k] = W2^T*scl hi        4032
#define OFF_B3L   9152     //                          lo             4032
#define OFF_AH    13184    // bf16 [128 row][72 k] activations hi     4608
#define OFF_AL    17792    //                          lo             4608
#define OFF_US    22400    // [128][4] unit vectors                   512
#define OFF_EMBT  22912    // [8][128] radial embedding (k-major)     1024
#define OFF_SVS   23936    // [128][84] gathered sender s|v           10752
#define OFF_DOTS  34688    // [128][16] v.u                           2048
#define OFF_MIXS  36736    // [128][116] gates (112 + pad)            14848
#define MIX_STRIDE 116
#define SMEM_FLOATS 51584
#define SMEM_BYTES (SMEM_FLOATS * 4)

__device__ __forceinline__ float swishf(float x) {
    return x * (1.0f / (1.0f + __expf(-x)));
}

// split two fp32 into packed bf16 hi-pair and lo-pair (x0 in low half)
__device__ __forceinline__ void split2(float x0, float x1, uint32_t& h, uint32_t& l) {
    __nv_bfloat162 hb = __floats2bfloat162_rn(x0, x1);
    float r0 = x0 - __bfloat162float(hb.x);
    float r1 = x1 - __bfloat162float(hb.y);
    __nv_bfloat162 lb = __floats2bfloat162_rn(r0, r1);
    h = *(uint32_t*)&hb;
    l = *(uint32_t*)&lb;
}

__device__ __forceinline__ void mma_bf16(float* d, uint32_t a0, uint32_t a1,
                                         uint32_t a2, uint32_t a3,
                                         uint32_t b0, uint32_t b1) {
    asm volatile(
        "mma.sync.aligned.m16n8k16.row.col.f32.bf16.bf16.f32 "
        "{%0,%1,%2,%3}, {%4,%5,%6,%7}, {%8,%9}, {%0,%1,%2,%3};"
        : "+f"(d[0]), "+f"(d[1]), "+f"(d[2]), "+f"(d[3])
        : "r"(a0), "r"(a1), "r"(a2), "r"(a3), "r"(b0), "r"(b1));
}

extern "C" __global__ void __launch_bounds__(THREADS, 1)
mp_kernel(const float* __restrict__ vectors,
          const float* __restrict__ node_s,
          const float* __restrict__ node_v,
          const float* __restrict__ W0,
          const float* __restrict__ W1,
          const float* __restrict__ W2,
          const int* __restrict__ senders,
          const int* __restrict__ receivers,
          float* __restrict__ out,
          int E, int numTiles)
{
    extern __shared__ float sm[];
    uint32_t* smw = (uint32_t*)sm;
    const int t = threadIdx.x;

    // ---- one-time weight staging ----
    for (int i = t; i < 512; i += THREADS) sm[OFF_W0 + i] = W0[i] * 0.35355339059327373f;
    for (int i = t; i < 64 * 32; i += THREADS) {      // B2[n][k] = W1[k][n]/8
        int n = i >> 5, kp = i & 31;
        float x0 = W1[(2*kp)   * 64 + n] * 0.125f;
        float x1 = W1[(2*kp+1) * 64 + n] * 0.125f;
        uint32_t hw, lw;
        split2(x0, x1, hw, lw);
        smw[OFF_B2H + n * ASTRIDE + kp] = hw;
        smw[OFF_B2L + n * ASTRIDE + kp] = lw;
    }
    for (int i = t; i < 112 * 32; i += THREADS) {     // B3[n][k] = W2[k][n]*scl(n)
        int n = i >> 5, kp = i & 31;
        float scl = (n >= 96) ? 0.03125f * 1.224744871391589f : 0.03125f;
        float x0 = W2[(2*kp)   * 112 + n] * scl;
        float x1 = W2[(2*kp+1) * 112 + n] * scl;
        uint32_t hw, lw;
        split2(x0, x1, hw, lw);
        smw[OFF_B3H + n * ASTRIDE + kp] = hw;
        smw[OFF_B3L + n * ASTRIDE + kp] = lw;
    }
    __syncthreads();

    const int w = t >> 5, lane = t & 31;
    const int g = lane >> 2, tq = lane & 3;           // fragment group / thread-in-group
    const int mstrip = w >> 1, nhalf = w & 1;
    const int mb = mstrip * 16;

    for (int tile = blockIdx.x; tile < numTiles; tile += gridDim.x) {
        const int e0 = tile * TE;

        // ---- stage A: geometry + radial (Bessel*envelope) embedding ----
        if (t < TE) {
            int e = e0 + t;
            float vx = 0.f, vy = 0.f, vz = 0.f;
            if (e < E) { vx = vectors[3*e+0]; vy = vectors[3*e+1]; vz = vectors[3*e+2]; }
            float r = sqrtf(vx*vx + vy*vy + vz*vz);
            float rinv = (r > 1e-12f) ? 1.0f / r : 0.0f;
            sm[OFF_US + 4*t+0] = vx*rinv; sm[OFF_US + 4*t+1] = vy*rinv;
            sm[OFF_US + 4*t+2] = vz*rinv; sm[OFF_US + 4*t+3] = 0.f;
            float env = 0.0f;
            if (r < 1.0f) {
                float x2 = r*r, x4 = x2*x2, x6 = x4*x2, x7 = x6*r, x8 = x4*x4;
                env = 1.0f - 28.0f*x6 + 48.0f*x7 - 21.0f*x8;
            }
            float pref = (r > 0.0f) ? 1.4142135623730951f * rinv * env : 0.0f;
            float s1, c1;
            sincosf(3.14159265358979323846f * r, &s1, &c1);
            float sn = s1, sp = 0.0f, c2 = 2.0f * c1;
            #pragma unroll
            for (int n = 0; n < 8; n++) {
                sm[OFF_EMBT + n*TE + t] = pref * sn;
                float nx = c2 * sn - sp; sp = sn; sn = nx;
            }
        }
        // gather issue (latency hidden behind stage B)
        const int ge = t >> 2, gsub = t & 3;
        const int geg = e0 + ge;
        const bool gok = (geg < E);
        int snd = gok ? senders[geg] : 0;
        const float4* sp4 = (const float4*)(node_s + (size_t)snd * 32);
        const float4* vp4 = (const float4*)(node_v + (size_t)snd * 48);
        float4 gr[5];
        #pragma unroll
        for (int q = 0; q < 5; q++) {
            int f4i = gsub + 4*q;
            float4 val = {0.f, 0.f, 0.f, 0.f};
            if (gok) val = (f4i < 8) ? sp4[f4i] : vp4[f4i - 8];
            gr[q] = val;
        }
        __syncthreads();

        // ---- stage B: GEMM1 (FFMA, K=8), fragment-layout output -> split bf16 A ----
        {
            const int nb = nhalf * 32;
            float acc[2][4][2];
            #pragma unroll
            for (int a = 0; a < 2; a++)
                #pragma unroll
                for (int b = 0; b < 4; b++) { acc[a][b][0] = 0.f; acc[a][b][1] = 0.f; }
            #pragma unroll
            for (int k = 0; k < 8; k++) {
                float e0v = sm[OFF_EMBT + k*TE + mb + g];
                float e1v = sm[OFF_EMBT + k*TE + mb + 8 + g];
                #pragma unroll
                for (int nt = 0; nt < 4; nt++) {
                    float2 wv = *(const float2*)(sm + OFF_W0 + k*64 + nb + nt*8 + 2*tq);
                    acc[0][nt][0] += e0v * wv.x; acc[0][nt][1] += e0v * wv.y;
                    acc[1][nt][0] += e1v * wv.x; acc[1][nt][1] += e1v * wv.y;
                }
            }
            #pragma unroll
            for (int rh = 0; rh < 2; rh++) {
                int row = mb + g + 8*rh;
                #pragma unroll
                for (int nt = 0; nt < 4; nt++) {
                    uint32_t hw, lw;
                    split2(swishf(acc[rh][nt][0]), swishf(acc[rh][nt][1]), hw, lw);
                    int word = row * ASTRIDE + (nb + nt*8) / 2 + tq;
                    smw[OFF_AH + word] = hw;
                    smw[OFF_AL + word] = lw;
                }
            }
        }
        // land gather into smem; compute dots
        {
            float* dst = sm + OFF_SVS + ge * 84;
            #pragma unroll
            for (int q = 0; q < 5; q++) *(float4*)(dst + 4 * (gsub + 4*q)) = gr[q];
            __syncwarp();
            const float* usf = sm + OFF_US + 4 * ge;
            float ux = usf[0], uy = usf[1], uz = usf[2];
            #pragma unroll
            for (int q = 0; q < 4; q++) {
                int c = 4 * gsub + q;
                const float* vv = dst + 32 + 3 * c;
                sm[OFF_DOTS + ge * 16 + c] = ux*vv[0] + uy*vv[1] + uz*vv[2];
            }
        }
        __syncthreads();

        // ---- stage C: GEMM2 via bf16 mma (3-pass split), M128 N64 K64 ----
        float acc2[4][4];
        {
            const int nb = nhalf * 32;
            #pragma unroll
            for (int n = 0; n < 4; n++)
                #pragma unroll
                for (int j = 0; j < 4; j++) acc2[n][j] = 0.f;
            #pragma unroll
            for (int k = 0; k < 4; k++) {
                int ar0 = (mb + g) * ASTRIDE + k*8 + tq;
                int ar1 = (mb + g + 8) * ASTRIDE + k*8 + tq;
                uint32_t ah0 = smw[OFF_AH + ar0], ah1 = smw[OFF_AH + ar1];
                uint32_t ah2 = smw[OFF_AH + ar0 + 4], ah3 = smw[OFF_AH + ar1 + 4];
                uint32_t al0 = smw[OFF_AL + ar0], al1 = smw[OFF_AL + ar1];
                uint32_t al2 = smw[OFF_AL + ar0 + 4], al3 = smw[OFF_AL + ar1 + 4];
                #pragma unroll
                for (int n = 0; n < 4; n++) {
                    int br = (nb + n*8 + g) * ASTRIDE + k*8 + tq;
                    uint32_t bh0 = smw[OFF_B2H + br], bh1 = smw[OFF_B2H + br + 4];
                    uint32_t bl0 = smw[OFF_B2L + br], bl1 = smw[OFF_B2L + br + 4];
                    mma_bf16(acc2[n], ah0, ah1, ah2, ah3, bh0, bh1);
                    mma_bf16(acc2[n], ah0, ah1, ah2, ah3, bl0, bl1);
                    mma_bf16(acc2[n], al0, al1, al2, al3, bh0, bh1);
                }
            }
        }
        __syncthreads();   // all h1 reads done before overwrite

        // ---- stage D: swish(h2), split -> A arrays (fragment store, conflict-free) ----
        {
            const int nb = nhalf * 32;
            #pragma unroll
            for (int n = 0; n < 4; n++) {
                uint32_t hw0, lw0, hw1, lw1;
                split2(swishf(acc2[n][0]), swishf(acc2[n][1]), hw0, lw0);
                split2(swishf(acc2[n][2]), swishf(acc2[n][3]), hw1, lw1);
                int w0i = (mb + g) * ASTRIDE + (nb + n*8) / 2 + tq;
                int w1i = (mb + g + 8) * ASTRIDE + (nb + n*8) / 2 + tq;
                smw[OFF_AH + w0i] = hw0; smw[OFF_AL + w0i] = lw0;
                smw[OFF_AH + w1i] = hw1; smw[OFF_AL + w1i] = lw1;
            }
        }
        __syncthreads();

        // ---- stage E: GEMM3 via bf16 mma (3-pass split), M128 N112 K64 -> mixs ----
        {
            const int nb3 = nhalf * 56;
            float acc3[7][4];
            #pragma unroll
            for (int n = 0; n < 7; n++)
                #pragma unroll
                for (int j = 0; j < 4; j++) acc3[n][j] = 0.f;
            #pragma unroll
            for (int k = 0; k < 4; k++) {
                int ar0 = (mb + g) * ASTRIDE + k*8 + tq;
                int ar1 = (mb + g + 8) * ASTRIDE + k*8 + tq;
                uint32_t ah0 = smw[OFF_AH + ar0], ah1 = smw[OFF_AH + ar1];
                uint32_t ah2 = smw[OFF_AH + ar0 + 4], ah3 = smw[OFF_AH + ar1 + 4];
                uint32_t al0 = smw[OFF_AL + ar0], al1 = smw[OFF_AL + ar1];
                uint32_t al2 = smw[OFF_AL + ar0 + 4], al3 = smw[OFF_AL + ar1 + 4];
                #pragma unroll
                for (int n = 0; n < 7; n++) {
                    int br = (nb3 + n*8 + g) * ASTRIDE + k*8 + tq;
                    uint32_t bh0 = smw[OFF_B3H + br], bh1 = smw[OFF_B3H + br + 4];
                    uint32_t bl0 = smw[OFF_B3L + br], bl1 = smw[OFF_B3L + br + 4];
                    mma_bf16(acc3[n], ah0, ah1, ah2, ah3, bh0, bh1);
                    mma_bf16(acc3[n], ah0, ah1, ah2, ah3, bl0, bl1);
                    mma_bf16(acc3[n], al0, al1, al2, al3, bh0, bh1);
                }
            }
            #pragma unroll
            for (int n = 0; n < 7; n++) {
                int col = nb3 + n*8 + 2*tq;
                *(float2*)(sm + OFF_MIXS + (mb + g) * MIX_STRIDE + col) =
                    make_float2(acc3[n][0], acc3[n][1]);
                *(float2*)(sm + OFF_MIXS + (mb + g + 8) * MIX_STRIDE + col) =
                    make_float2(acc3[n][2], acc3[n][3]);
            }
        }
        __syncthreads();

        // ---- stage G: message formation + vectorized atomic scatter ----
        {
            const int e = t >> 2, sub = t & 3;
            const int eg2 = e0 + e;
            const bool ok = (eg2 < E);
            int rec = ok ? receivers[eg2] : 0;
            const float* dst = sm + OFF_SVS + e * 84;
            const float* usf = sm + OFF_US + 4 * e;
            const float* dts = sm + OFF_DOTS + e * 16;
            const float* mx  = sm + OFF_MIXS + e * MIX_STRIDE;
            float* obase = out + (size_t)rec * 240;

            #pragma unroll
            for (int it = 0; it < 15; it++) {
                int gg = 4 * it + sub;   // warp-uniform region per it
                float4 val;
                if (gg < 8) {            // msg_s: s * gate
                    float4 s4 = *(const float4*)(dst + 4 * gg);
                    float4 m4 = *(const float4*)(mx + 4 * gg);
                    val.x = s4.x*m4.x; val.y = s4.y*m4.y; val.z = s4.z*m4.z; val.w = s4.w*m4.w;
                } else if (gg < 12) {    // msg_s: (v.u) * gate
                    float4 d4 = *(const float4*)(dts + (4 * gg - 32));
                    float4 m4 = *(const float4*)(mx + 4 * gg);
                    val.x = d4.x*m4.x; val.y = d4.y*m4.y; val.z = d4.z*m4.z; val.w = d4.w*m4.w;
                } else {                 // msg_v flat: [v | s*u | u(u.v)-v/3] * gate (sqrt1.5 folded)
                    int j0 = 4 * gg - 48;
                    float tmp[4];
                    #pragma unroll
                    for (int q2 = 0; q2 < 4; q2++) {
                        int j = j0 + q2;
                        int ch = j / 3;
                        int i  = j - 3 * ch;
                        float m = mx[48 + ch];
                        float x;
                        if (ch < 16)      x = dst[32 + j];
                        else if (ch < 48) x = dst[ch - 16] * usf[i];
                        else {
                            int c2 = ch - 48;
                            x = usf[i]*dts[c2] - dst[32 + 3*c2 + i] * 0.3333333333333333f;
                        }
                        tmp[q2] = x * m;
                    }
                    val.x = tmp[0]; val.y = tmp[1]; val.z = tmp[2]; val.w = tmp[3];
                }
                if (ok) {
                    float* addr = obase + 4 * gg;
                    asm volatile("red.global.add.v4.f32 [%0], {%1,%2,%3,%4};"
                                 :: "l"(addr), "f"(val.x), "f"(val.y), "f"(val.z), "f"(val.w)
                                 : "memory");
                }
            }
        }
        __syncthreads();   // smem reused next tile
    }
}

extern "C" void kernel_launch(void* const* d_in, const int* in_sizes, int n_in,
                              void* d_out, int out_size) {
    const float* vectors   = (const float*)d_in[0];
    const float* node_s    = (const float*)d_in[1];
    const float* node_v    = (const float*)d_in[2];
    const float* W0        = (const float*)d_in[3];
    const float* W1        = (const float*)d_in[4];
    const float* W2        = (const float*)d_in[5];
    const int*   senders   = (const int*)d_in[6];
    const int*   receivers = (const int*)d_in[7];
    float*       out       = (float*)d_out;

    int E = in_sizes[6];
    int numTiles = (E + TE - 1) / TE;

    cudaFuncSetAttribute(mp_kernel, cudaFuncAttributeMaxDynamicSharedMemorySize, SMEM_BYTES);

    cudaMemsetAsync(d_out, 0, (size_t)out_size * sizeof(float), 0);

    int grid = 148;                      // persistent: 1 block/SM (smem-bound)
    if (grid > numTiles) grid = numTiles;
    mp_kernel<<<grid, THREADS, SMEM_BYTES>>>(vectors, node_s, node_v, W0, W1, W2,
                                             senders, receivers, out, E, numTiles);
}

// round 5
// speedup vs baseline: 1.6397x; 1.0855x over previous
#include <cuda_runtime.h>
#include <cuda_bf16.h>
#include <math.h>
#include <stdint.h>

#define TE 64
#define THREADS 256

// ---- smem layout (32-bit word offsets) ----
// bf16 matrices use row stride 72 bf16 = 36 words (64 data + 8 pad)
#define ASTRIDE 36
#define OFF_W0    0        // fp32 [8][64] folded 1/sqrt(8)             512
#define OFF_B2H   512      // bf16 [64 n][72 k]  = W1^T/8 hi            2304
#define OFF_B2L   2816     //                          lo               2304
#define OFF_B3H   5120     // bf16 [112 n][72 k] = W2^T*scl hi          4032
#define OFF_B3L   9152     //                          lo               4032
// union region: AH/AL/EMBT alias MIXS (gates written after last A read)
#define OFF_AH    13184    // bf16 [64 row][72 k] act hi                2304
#define OFF_AL    15488    //                      lo                   2304
#define OFF_EMBT  17792    // fp32 [8][64] radial embedding             512
#define OFF_MIXS  13184    // fp32 [64][116] gates  (aliases above)     7424
#define OFF_US    20608    // [64][4] unit vectors                      256
#define OFF_SVS   20864    // [64][84] gathered sender s|v              5376
#define OFF_DOTS  26240    // [64][16] v.u                              1024
#define MIX_STRIDE 116
#define SMEM_FLOATS 27264
#define SMEM_BYTES (SMEM_FLOATS * 4)   // 109056 B -> 2 CTAs/SM

__device__ __forceinline__ float swishf(float x) {
    return x * (1.0f / (1.0f + __expf(-x)));
}

// split two fp32 into packed bf16 hi-pair and lo-pair (x0 in low half)
__device__ __forceinline__ void split2(float x0, float x1, uint32_t& h, uint32_t& l) {
    __nv_bfloat162 hb = __floats2bfloat162_rn(x0, x1);
    float r0 = x0 - __bfloat162float(hb.x);
    float r1 = x1 - __bfloat162float(hb.y);
    __nv_bfloat162 lb = __floats2bfloat162_rn(r0, r1);
    h = *(uint32_t*)&hb;
    l = *(uint32_t*)&lb;
}

__device__ __forceinline__ void mma_bf16(float* d, uint32_t a0, uint32_t a1,
                                         uint32_t a2, uint32_t a3,
                                         uint32_t b0, uint32_t b1) {
    asm volatile(
        "mma.sync.aligned.m16n8k16.row.col.f32.bf16.bf16.f32 "
        "{%0,%1,%2,%3}, {%4,%5,%6,%7}, {%8,%9}, {%0,%1,%2,%3};"
        : "+f"(d[0]), "+f"(d[1]), "+f"(d[2]), "+f"(d[3])
        : "r"(a0), "r"(a1), "r"(a2), "r"(a3), "r"(b0), "r"(b1));
}

extern "C" __global__ void __launch_bounds__(THREADS, 2)
mp_kernel(const float* __restrict__ vectors,
          const float* __restrict__ node_s,
          const float* __restrict__ node_v,
          const float* __restrict__ W0,
          const float* __restrict__ W1,
          const float* __restrict__ W2,
          const int* __restrict__ senders,
          const int* __restrict__ receivers,
          float* __restrict__ out,
          int E, int numTiles)
{
    extern __shared__ float sm[];
    uint32_t* smw = (uint32_t*)sm;
    const int t = threadIdx.x;

    // ---- one-time weight staging ----
    for (int i = t; i < 512; i += THREADS) sm[OFF_W0 + i] = W0[i] * 0.35355339059327373f;
    for (int i = t; i < 64 * 32; i += THREADS) {      // B2[n][k] = W1[k][n]/8
        int n = i >> 5, kp = i & 31;
        float x0 = W1[(2*kp)   * 64 + n] * 0.125f;
        float x1 = W1[(2*kp+1) * 64 + n] * 0.125f;
        uint32_t hw, lw;
        split2(x0, x1, hw, lw);
        smw[OFF_B2H + n * ASTRIDE + kp] = hw;
        smw[OFF_B2L + n * ASTRIDE + kp] = lw;
    }
    for (int i = t; i < 112 * 32; i += THREADS) {     // B3[n][k] = W2[k][n]*scl(n)
        int n = i >> 5, kp = i & 31;
        float scl = (n >= 96) ? 0.03125f * 1.224744871391589f : 0.03125f;
        float x0 = W2[(2*kp)   * 112 + n] * scl;
        float x1 = W2[(2*kp+1) * 112 + n] * scl;
        uint32_t hw, lw;
        split2(x0, x1, hw, lw);
        smw[OFF_B3H + n * ASTRIDE + kp] = hw;
        smw[OFF_B3L + n * ASTRIDE + kp] = lw;
    }
    __syncthreads();

    const int w = t >> 5, lane = t & 31;
    const int g = lane >> 2, tq = lane & 3;           // fragment group / thread-in-group
    const int mstrip = w >> 1, nhalf = w & 1;         // 4 M-strips x 2 N-halves
    const int mb = mstrip * 16;

    for (int tile = blockIdx.x; tile < numTiles; tile += gridDim.x) {
        const int e0 = tile * TE;

        // ---- stage A: geometry + radial (Bessel*envelope) embedding ----
        if (t < TE) {
            int e = e0 + t;
            float vx = 0.f, vy = 0.f, vz = 0.f;
            if (e < E) { vx = vectors[3*e+0]; vy = vectors[3*e+1]; vz = vectors[3*e+2]; }
            float r = sqrtf(vx*vx + vy*vy + vz*vz);
            float rinv = (r > 1e-12f) ? 1.0f / r : 0.0f;
            sm[OFF_US + 4*t+0] = vx*rinv; sm[OFF_US + 4*t+1] = vy*rinv;
            sm[OFF_US + 4*t+2] = vz*rinv; sm[OFF_US + 4*t+3] = 0.f;
            float env = 0.0f;
            if (r < 1.0f) {
                float x2 = r*r, x4 = x2*x2, x6 = x4*x2, x7 = x6*r, x8 = x4*x4;
                env = 1.0f - 28.0f*x6 + 48.0f*x7 - 21.0f*x8;
            }
            float pref = (r > 0.0f) ? 1.4142135623730951f * rinv * env : 0.0f;
            float s1, c1;
            sincosf(3.14159265358979323846f * r, &s1, &c1);
            float sn = s1, sp = 0.0f, c2 = 2.0f * c1;
            #pragma unroll
            for (int n = 0; n < 8; n++) {
                sm[OFF_EMBT + n*TE + t] = pref * sn;
                float nx = c2 * sn - sp; sp = sn; sn = nx;
            }
        }
        // gather issue (latency hidden behind stage B)
        const int ge = t >> 2, gsub = t & 3;
        const int geg = e0 + ge;
        const bool gok = (geg < E);
        int snd = gok ? senders[geg] : 0;
        const float4* sp4 = (const float4*)(node_s + (size_t)snd * 32);
        const float4* vp4 = (const float4*)(node_v + (size_t)snd * 48);
        float4 gr[5];
        #pragma unroll
        for (int q = 0; q < 5; q++) {
            int f4i = gsub + 4*q;
            float4 val = {0.f, 0.f, 0.f, 0.f};
            if (gok) val = (f4i < 8) ? sp4[f4i] : vp4[f4i - 8];
            gr[q] = val;
        }
        __syncthreads();

        // ---- stage B: GEMM1 (FFMA, K=8), fragment-layout output -> split bf16 A ----
        {
            const int nb = nhalf * 32;
            float acc[2][4][2];
            #pragma unroll
            for (int a = 0; a < 2; a++)
                #pragma unroll
                for (int b = 0; b < 4; b++) { acc[a][b][0] = 0.f; acc[a][b][1] = 0.f; }
            #pragma unroll
            for (int k = 0; k < 8; k++) {
                float e0v = sm[OFF_EMBT + k*TE + mb + g];
                float e1v = sm[OFF_EMBT + k*TE + mb + 8 + g];
                #pragma unroll
                for (int nt = 0; nt < 4; nt++) {
                    float2 wv = *(const float2*)(sm + OFF_W0 + k*64 + nb + nt*8 + 2*tq);
                    acc[0][nt][0] += e0v * wv.x; acc[0][nt][1] += e0v * wv.y;
                    acc[1][nt][0] += e1v * wv.x; acc[1][nt][1] += e1v * wv.y;
                }
            }
            #pragma unroll
            for (int rh = 0; rh < 2; rh++) {
                int row = mb + g + 8*rh;
                #pragma unroll
                for (int nt = 0; nt < 4; nt++) {
                    uint32_t hw, lw;
                    split2(swishf(acc[rh][nt][0]), swishf(acc[rh][nt][1]), hw, lw);
                    int word = row * ASTRIDE + (nb + nt*8) / 2 + tq;
                    smw[OFF_AH + word] = hw;
                    smw[OFF_AL + word] = lw;
                }
            }
        }
        // land gather into smem; compute dots
        {
            float* dst = sm + OFF_SVS + ge * 84;
            #pragma unroll
            for (int q = 0; q < 5; q++) *(float4*)(dst + 4 * (gsub + 4*q)) = gr[q];
            __syncwarp();
            const float* usf = sm + OFF_US + 4 * ge;
            float ux = usf[0], uy = usf[1], uz = usf[2];
            #pragma unroll
            for (int q = 0; q < 4; q++) {
                int c = 4 * gsub + q;
                const float* vv = dst + 32 + 3 * c;
                sm[OFF_DOTS + ge * 16 + c] = ux*vv[0] + uy*vv[1] + uz*vv[2];
            }
        }
        __syncthreads();

        // ---- stage C: GEMM2 via bf16 mma (3-pass split), M64 N64 K64 ----
        float acc2[4][4];
        {
            const int nb = nhalf * 32;
            #pragma unroll
            for (int n = 0; n < 4; n++)
                #pragma unroll
                for (int j = 0; j < 4; j++) acc2[n][j] = 0.f;
            #pragma unroll
            for (int k = 0; k < 4; k++) {
                int ar0 = (mb + g) * ASTRIDE + k*8 + tq;
                int ar1 = (mb + g + 8) * ASTRIDE + k*8 + tq;
                uint32_t ah0 = smw[OFF_AH + ar0], ah1 = smw[OFF_AH + ar1];
                uint32_t ah2 = smw[OFF_AH + ar0 + 4], ah3 = smw[OFF_AH + ar1 + 4];
                uint32_t al0 = smw[OFF_AL + ar0], al1 = smw[OFF_AL + ar1];
                uint32_t al2 = smw[OFF_AL + ar0 + 4], al3 = smw[OFF_AL + ar1 + 4];
                #pragma unroll
                for (int n = 0; n < 4; n++) {
                    int br = (nb + n*8 + g) * ASTRIDE + k*8 + tq;
                    uint32_t bh0 = smw[OFF_B2H + br], bh1 = smw[OFF_B2H + br + 4];
                    uint32_t bl0 = smw[OFF_B2L + br], bl1 = smw[OFF_B2L + br + 4];
                    mma_bf16(acc2[n], ah0, ah1, ah2, ah3, bh0, bh1);
                    mma_bf16(acc2[n], ah0, ah1, ah2, ah3, bl0, bl1);
                    mma_bf16(acc2[n], al0, al1, al2, al3, bh0, bh1);
                }
            }
        }
        __syncthreads();   // all h1 reads done before overwrite

        // ---- stage D: swish(h2), split -> A arrays (fragment store, conflict-free) ----
        {
            const int nb = nhalf * 32;
            #pragma unroll
            for (int n = 0; n < 4; n++) {
                uint32_t hw0, lw0, hw1, lw1;
                split2(swishf(acc2[n][0]), swishf(acc2[n][1]), hw0, lw0);
                split2(swishf(acc2[n][2]), swishf(acc2[n][3]), hw1, lw1);
                int w0i = (mb + g) * ASTRIDE + (nb + n*8) / 2 + tq;
                int w1i = (mb + g + 8) * ASTRIDE + (nb + n*8) / 2 + tq;
                smw[OFF_AH + w0i] = hw0; smw[OFF_AL + w0i] = lw0;
                smw[OFF_AH + w1i] = hw1; smw[OFF_AL + w1i] = lw1;
            }
        }
        __syncthreads();

        // ---- stage E: GEMM3 via bf16 mma (3-pass split), M64 N112 K64 -> mixs ----
        {
            const int nb3 = nhalf * 56;
            float acc3[7][4];
            #pragma unroll
            for (int n = 0; n < 7; n++)
                #pragma unroll
                for (int j = 0; j < 4; j++) acc3[n][j] = 0.f;
            #pragma unroll
            for (int k = 0; k < 4; k++) {
                int ar0 = (mb + g) * ASTRIDE + k*8 + tq;
                int ar1 = (mb + g + 8) * ASTRIDE + k*8 + tq;
                uint32_t ah0 = smw[OFF_AH + ar0], ah1 = smw[OFF_AH + ar1];
                uint32_t ah2 = smw[OFF_AH + ar0 + 4], ah3 = smw[OFF_AH + ar1 + 4];
                uint32_t al0 = smw[OFF_AL + ar0], al1 = smw[OFF_AL + ar1];
                uint32_t al2 = smw[OFF_AL + ar0 + 4], al3 = smw[OFF_AL + ar1 + 4];
                #pragma unroll
                for (int n = 0; n < 7; n++) {
                    int br = (nb3 + n*8 + g) * ASTRIDE + k*8 + tq;
                    uint32_t bh0 = smw[OFF_B3H + br], bh1 = smw[OFF_B3H + br + 4];
                    uint32_t bl0 = smw[OFF_B3L + br], bl1 = smw[OFF_B3L + br + 4];
                    mma_bf16(acc3[n], ah0, ah1, ah2, ah3, bh0, bh1);
                    mma_bf16(acc3[n], ah0, ah1, ah2, ah3, bl0, bl1);
                    mma_bf16(acc3[n], al0, al1, al2, al3, bh0, bh1);
                }
            }
            __syncthreads();   // A/EMBT fully read everywhere before gate store aliases them
            #pragma unroll
            for (int n = 0; n < 7; n++) {
                int col = nb3 + n*8 + 2*tq;
                *(float2*)(sm + OFF_MIXS + (mb + g) * MIX_STRIDE + col) =
                    make_float2(acc3[n][0], acc3[n][1]);
                *(float2*)(sm + OFF_MIXS + (mb + g + 8) * MIX_STRIDE + col) =
                    make_float2(acc3[n][2], acc3[n][3]);
            }
        }
        __syncthreads();

        // ---- stage G: message formation + vectorized atomic scatter ----
        {
            const int e = t >> 2, sub = t & 3;
            const int eg2 = e0 + e;
            const bool ok = (eg2 < E);
            int rec = ok ? receivers[eg2] : 0;
            const float* dst = sm + OFF_SVS + e * 84;
            const float* usf = sm + OFF_US + 4 * e;
            const float* dts = sm + OFF_DOTS + e * 16;
            const float* mx  = sm + OFF_MIXS + e * MIX_STRIDE;
            float* obase = out + (size_t)rec * 240;

            #pragma unroll
            for (int it = 0; it < 15; it++) {
                int gg = 4 * it + sub;   // warp-uniform region per it
                float4 val;
                if (gg < 8) {            // msg_s: s * gate
                    float4 s4 = *(const float4*)(dst + 4 * gg);
                    float4 m4 = *(const float4*)(mx + 4 * gg);
                    val.x = s4.x*m4.x; val.y = s4.y*m4.y; val.z = s4.z*m4.z; val.w = s4.w*m4.w;
                } else if (gg < 12) {    // msg_s: (v.u) * gate
                    float4 d4 = *(const float4*)(dts + (4 * gg - 32));
                    float4 m4 = *(const float4*)(mx + 4 * gg);
                    val.x = d4.x*m4.x; val.y = d4.y*m4.y; val.z = d4.z*m4.z; val.w = d4.w*m4.w;
                } else {                 // msg_v flat: [v | s*u | u(u.v)-v/3] * gate (sqrt1.5 folded)
                    int j0 = 4 * gg - 48;
                    float tmp[4];
                    #pragma unroll
                    for (int q2 = 0; q2 < 4; q2++) {
                        int j = j0 + q2;
                        int ch = j / 3;
                        int i  = j - 3 * ch;
                        float m = mx[48 + ch];
                        float x;
                        if (ch < 16)      x = dst[32 + j];
                        else if (ch < 48) x = dst[ch - 16] * usf[i];
                        else {
                            int c2 = ch - 48;
                            x = usf[i]*dts[c2] - dst[32 + 3*c2 + i] * 0.3333333333333333f;
                        }
                        tmp[q2] = x * m;
                    }
                    val.x = tmp[0]; val.y = tmp[1]; val.z = tmp[2]; val.w = tmp[3];
                }
                if (ok) {
                    float* addr = obase + 4 * gg;
                    asm volatile("red.global.add.v4.f32 [%0], {%1,%2,%3,%4};"
                                 :: "l"(addr), "f"(val.x), "f"(val.y), "f"(val.z), "f"(val.w)
                                 : "memory");
                }
            }
        }
        __syncthreads();   // smem reused next tile
    }
}

extern "C" void kernel_launch(void* const* d_in, const int* in_sizes, int n_in,
                              void* d_out, int out_size) {
    const float* vectors   = (const float*)d_in[0];
    const float* node_s    = (const float*)d_in[1];
    const float* node_v    = (const float*)d_in[2];
    const float* W0        = (const float*)d_in[3];
    const float* W1        = (const float*)d_in[4];
    const float* W2        = (const float*)d_in[5];
    const int*   senders   = (const int*)d_in[6];
    const int*   receivers = (const int*)d_in[7];
    float*       out       = (float*)d_out;

    int E = in_sizes[6];
    int numTiles = (E + TE - 1) / TE;

    cudaFuncSetAttribute(mp_kernel, cudaFuncAttributeMaxDynamicSharedMemorySize, SMEM_BYTES);

    cudaMemsetAsync(d_out, 0, (size_t)out_size * sizeof(float), 0);

    int grid = 296;                      // persistent: 2 CTAs/SM
    if (grid > numTiles) grid = numTiles;
    mp_kernel<<<grid, THREADS, SMEM_BYTES>>>(vectors, node_s, node_v, W0, W1, W2,
                                             senders, receivers, out, E, numTiles);
}

// round 6
// speedup vs baseline: 1.8443x; 1.1248x over previous
#include <cuda_runtime.h>
#include <cuda_bf16.h>
#include <math.h>
#include <stdint.h>

#define TE 64
#define THREADS 256

// ---- smem layout (32-bit word offsets) ----
#define OFF_W0    0        // fp32 [8][64] folded 1/sqrt(8)               512
#define OFF_B2    512      // packed units [64 n][4 k][4 tq][16B]         4096
#define OFF_B3    4608     // packed units [112 n][4 k][4 tq][16B]        7168
// union region: A-frags + EMBT alias MIXS
#define OFF_AHI   11776    // A hi frag units [4 ms][4 k][8 g][4 tq]      2048
#define OFF_ALO   13824    // A lo                                        2048
#define OFF_EMBT  15872    // fp32 [8][64]                                512
#define OFF_MIXS  11776    // fp32 [64][116] gates (aliases above)        7424
#define OFF_US    19200    // [64][4]                                     256
#define OFF_SVS   19456    // [64][84]                                    5376
#define OFF_DOTS  24832    // [64][16]                                    1024
#define MIX_STRIDE 116
#define SMEM_FLOATS 25856
#define SMEM_BYTES (SMEM_FLOATS * 4)   // 103424 B -> 2 CTAs/SM

__device__ __forceinline__ float swishf(float x) {
    return x * (1.0f / (1.0f + __expf(-x)));
}

__device__ __forceinline__ void split2(float x0, float x1, uint32_t& h, uint32_t& l) {
    __nv_bfloat162 hb = __floats2bfloat162_rn(x0, x1);
    float r0 = x0 - __bfloat162float(hb.x);
    float r1 = x1 - __bfloat162float(hb.y);
    __nv_bfloat162 lb = __floats2bfloat162_rn(r0, r1);
    h = *(uint32_t*)&hb;
    l = *(uint32_t*)&lb;
}

__device__ __forceinline__ void mma_bf16(float* d, uint32_t a0, uint32_t a1,
                                         uint32_t a2, uint32_t a3,
                                         uint32_t b0, uint32_t b1) {
    asm volatile(
        "mma.sync.aligned.m16n8k16.row.col.f32.bf16.bf16.f32 "
        "{%0,%1,%2,%3}, {%4,%5,%6,%7}, {%8,%9}, {%0,%1,%2,%3};"
        : "+f"(d[0]), "+f"(d[1]), "+f"(d[2]), "+f"(d[3])
        : "r"(a0), "r"(a1), "r"(a2), "r"(a3), "r"(b0), "r"(b1));
}

extern "C" __global__ void __launch_bounds__(THREADS, 2)
mp_kernel(const float* __restrict__ vectors,
          const float* __restrict__ node_s,
          const float* __restrict__ node_v,
          const float* __restrict__ W0,
          const float* __restrict__ W1,
          const float* __restrict__ W2,
          const int* __restrict__ senders,
          const int* __restrict__ receivers,
          float* __restrict__ out,
          int E, int numTiles)
{
    extern __shared__ float sm[];
    uint32_t* smw = (uint32_t*)sm;
    const int t = threadIdx.x;

    // ---- one-time weight staging (packed 16B units, swizzled) ----
    for (int i = t; i < 512; i += THREADS) sm[OFF_W0 + i] = W0[i] * 0.35355339059327373f;
    for (int i = t; i < 64 * 32; i += THREADS) {      // B2[n][k] = W1[k][n]/8
        int n = i >> 5, wd = i & 31;
        int k = wd >> 3, r = wd & 7, tq = r & 3, half = r >> 2;
        float x0 = W1[(2*wd)   * 64 + n] * 0.125f;
        float x1 = W1[(2*wd+1) * 64 + n] * 0.125f;
        uint32_t hw, lw;
        split2(x0, x1, hw, lw);
        int kk = (k + n) & 3;
        int base = OFF_B2 + (n * 16 + kk * 4 + tq) * 4;
        smw[base + half] = hw;
        smw[base + 2 + half] = lw;
    }
    for (int i = t; i < 112 * 32; i += THREADS) {     // B3[n][k] = W2[k][n]*scl(n)
        int n = i >> 5, wd = i & 31;
        int k = wd >> 3, r = wd & 7, tq = r & 3, half = r >> 2;
        float scl = (n >= 96) ? 0.03125f * 1.224744871391589f : 0.03125f;
        float x0 = W2[(2*wd)   * 112 + n] * scl;
        float x1 = W2[(2*wd+1) * 112 + n] * scl;
        uint32_t hw, lw;
        split2(x0, x1, hw, lw);
        int kk = (k + n) & 3;
        int base = OFF_B3 + (n * 16 + kk * 4 + tq) * 4;
        smw[base + half] = hw;
        smw[base + 2 + half] = lw;
    }
    __syncthreads();

    const int w = t >> 5, lane = t & 31;
    const int g = lane >> 2, tq = lane & 3;
    const int mstrip = w >> 1, nhalf = w & 1;
    const int mb = mstrip * 16;
    const int aunit0 = (mstrip * 128 + g * 4 + tq) * 4;   // + k*128 words

    for (int tile = blockIdx.x; tile < numTiles; tile += gridDim.x) {
        const int e0 = tile * TE;

        // ---- stage A: geometry + radial embedding ----
        if (t < TE) {
            int e = e0 + t;
            float vx = 0.f, vy = 0.f, vz = 0.f;
            if (e < E) { vx = vectors[3*e+0]; vy = vectors[3*e+1]; vz = vectors[3*e+2]; }
            float r = sqrtf(vx*vx + vy*vy + vz*vz);
            float rinv = (r > 1e-12f) ? 1.0f / r : 0.0f;
            sm[OFF_US + 4*t+0] = vx*rinv; sm[OFF_US + 4*t+1] = vy*rinv;
            sm[OFF_US + 4*t+2] = vz*rinv; sm[OFF_US + 4*t+3] = 0.f;
            float env = 0.0f;
            if (r < 1.0f) {
                float x2 = r*r, x4 = x2*x2, x6 = x4*x2, x7 = x6*r, x8 = x4*x4;
                env = 1.0f - 28.0f*x6 + 48.0f*x7 - 21.0f*x8;
            }
            float pref = (r > 0.0f) ? 1.4142135623730951f * rinv * env : 0.0f;
            float s1, c1;
            sincosf(3.14159265358979323846f * r, &s1, &c1);
            float sn = s1, sp = 0.0f, c2 = 2.0f * c1;
            #pragma unroll
            for (int n = 0; n < 8; n++) {
                sm[OFF_EMBT + n*TE + t] = pref * sn;
                float nx = c2 * sn - sp; sp = sn; sn = nx;
            }
        }
        // gather issue (latency hidden behind stage B)
        const int ge = t >> 2, gsub = t & 3;
        const int geg = e0 + ge;
        const bool gok = (geg < E);
        int snd = gok ? senders[geg] : 0;
        const float4* sp4 = (const float4*)(node_s + (size_t)snd * 32);
        const float4* vp4 = (const float4*)(node_v + (size_t)snd * 48);
        float4 gr[5];
        #pragma unroll
        for (int q = 0; q < 5; q++) {
            int f4i = gsub + 4*q;
            float4 val = {0.f, 0.f, 0.f, 0.f};
            if (gok) val = (f4i < 8) ? sp4[f4i] : vp4[f4i - 8];
            gr[q] = val;
        }
        __syncthreads();

        // ---- stage B: GEMM1 (FFMA, K=8) -> packed A fragment units ----
        {
            const int nb = nhalf * 32;
            float acc[2][4][2];
            #pragma unroll
            for (int a = 0; a < 2; a++)
                #pragma unroll
                for (int b = 0; b < 4; b++) { acc[a][b][0] = 0.f; acc[a][b][1] = 0.f; }
            #pragma unroll
            for (int k = 0; k < 8; k++) {
                float e0v = sm[OFF_EMBT + k*TE + mb + g];
                float e1v = sm[OFF_EMBT + k*TE + mb + 8 + g];
                #pragma unroll
                for (int nt = 0; nt < 4; nt++) {
                    float2 wv = *(const float2*)(sm + OFF_W0 + k*64 + nb + nt*8 + 2*tq);
                    acc[0][nt][0] += e0v * wv.x; acc[0][nt][1] += e0v * wv.y;
                    acc[1][nt][0] += e1v * wv.x; acc[1][nt][1] += e1v * wv.y;
                }
            }
            #pragma unroll
            for (int kidx = 0; kidx < 2; kidx++) {
                int k = nhalf * 2 + kidx;
                int n0 = 2 * kidx, n1 = n0 + 1;
                uint32_t h0,l0,h1,l1,h2,l2,h3,l3;
                split2(swishf(acc[0][n0][0]), swishf(acc[0][n0][1]), h0, l0);
                split2(swishf(acc[1][n0][0]), swishf(acc[1][n0][1]), h1, l1);
                split2(swishf(acc[0][n1][0]), swishf(acc[0][n1][1]), h2, l2);
                split2(swishf(acc[1][n1][0]), swishf(acc[1][n1][1]), h3, l3);
                int au = aunit0 + k * 128;
                *(uint4*)(smw + OFF_AHI + au) = make_uint4(h0, h1, h2, h3);
                *(uint4*)(smw + OFF_ALO + au) = make_uint4(l0, l1, l2, l3);
            }
        }
        // land gather into smem; compute dots
        {
            float* dst = sm + OFF_SVS + ge * 84;
            #pragma unroll
            for (int q = 0; q < 5; q++) *(float4*)(dst + 4 * (gsub + 4*q)) = gr[q];
            __syncwarp();
            const float* usf = sm + OFF_US + 4 * ge;
            float ux = usf[0], uy = usf[1], uz = usf[2];
            #pragma unroll
            for (int q = 0; q < 4; q++) {
                int c = 4 * gsub + q;
                const float* vv = dst + 32 + 3 * c;
                sm[OFF_DOTS + ge * 16 + c] = ux*vv[0] + uy*vv[1] + uz*vv[2];
            }
        }
        __syncthreads();

        // ---- stage C: GEMM2 via bf16 mma (3-pass split), M64 N64 K64 ----
        float acc2[4][4];
        {
            const int nb = nhalf * 32;
            #pragma unroll
            for (int n = 0; n < 4; n++)
                #pragma unroll
                for (int j = 0; j < 4; j++) acc2[n][j] = 0.f;
            #pragma unroll
            for (int k = 0; k < 4; k++) {
                int au = aunit0 + k * 128;
                uint4 ah = *(const uint4*)(smw + OFF_AHI + au);
                uint4 al = *(const uint4*)(smw + OFF_ALO + au);
                #pragma unroll
                for (int n = 0; n < 4; n++) {
                    int row = nb + n*8 + g;
                    int kk = (k + row) & 3;
                    uint4 b = *(const uint4*)(smw + OFF_B2 + (row * 16 + kk * 4 + tq) * 4);
                    mma_bf16(acc2[n], ah.x, ah.y, ah.z, ah.w, b.x, b.y);
                    mma_bf16(acc2[n], ah.x, ah.y, ah.z, ah.w, b.z, b.w);
                    mma_bf16(acc2[n], al.x, al.y, al.z, al.w, b.x, b.y);
                }
            }
        }
        __syncthreads();   // all h1 reads done before overwrite

        // ---- stage D: swish(h2), split -> packed A fragment units ----
        {
            #pragma unroll
            for (int kidx = 0; kidx < 2; kidx++) {
                int k = nhalf * 2 + kidx;
                int n0 = 2 * kidx, n1 = n0 + 1;
                uint32_t h0,l0,h1,l1,h2,l2,h3,l3;
                split2(swishf(acc2[n0][0]), swishf(acc2[n0][1]), h0, l0);
                split2(swishf(acc2[n0][2]), swishf(acc2[n0][3]), h1, l1);
                split2(swishf(acc2[n1][0]), swishf(acc2[n1][1]), h2, l2);
                split2(swishf(acc2[n1][2]), swishf(acc2[n1][3]), h3, l3);
                int au = aunit0 + k * 128;
                *(uint4*)(smw + OFF_AHI + au) = make_uint4(h0, h1, h2, h3);
                *(uint4*)(smw + OFF_ALO + au) = make_uint4(l0, l1, l2, l3);
            }
        }
        __syncthreads();

        // ---- stage E: GEMM3 via bf16 mma (3-pass split), M64 N112 K64 -> mixs ----
        {
            const int nb3 = nhalf * 56;
            float acc3[7][4];
            #pragma unroll
            for (int n = 0; n < 7; n++)
                #pragma unroll
                for (int j = 0; j < 4; j++) acc3[n][j] = 0.f;
            #pragma unroll
            for (int k = 0; k < 4; k++) {
                int au = aunit0 + k * 128;
                uint4 ah = *(const uint4*)(smw + OFF_AHI + au);
                uint4 al = *(const uint4*)(smw + OFF_ALO + au);
                #pragma unroll
                for (int n = 0; n < 7; n++) {
                    int row = nb3 + n*8 + g;
                    int kk = (k + row) & 3;
                    uint4 b = *(const uint4*)(smw + OFF_B3 + (row * 16 + kk * 4 + tq) * 4);
                    mma_bf16(acc3[n], ah.x, ah.y, ah.z, ah.w, b.x, b.y);
                    mma_bf16(acc3[n], ah.x, ah.y, ah.z, ah.w, b.z, b.w);
                    mma_bf16(acc3[n], al.x, al.y, al.z, al.w, b.x, b.y);
                }
            }
            __syncthreads();   // A/EMBT fully read before gate store aliases them
            #pragma unroll
            for (int n = 0; n < 7; n++) {
                int col = nb3 + n*8 + 2*tq;
                *(float2*)(sm + OFF_MIXS + (mb + g) * MIX_STRIDE + col) =
                    make_float2(acc3[n][0], acc3[n][1]);
                *(float2*)(sm + OFF_MIXS + (mb + g + 8) * MIX_STRIDE + col) =
                    make_float2(acc3[n][2], acc3[n][3]);
            }
        }
        __syncthreads();

        // ---- stage G: message formation + vectorized atomic scatter ----
        {
            const int e = t >> 2, sub = t & 3;
            const int eg2 = e0 + e;
            const bool ok = (eg2 < E);
            int rec = ok ? receivers[eg2] : 0;
            const float* dst = sm + OFF_SVS + e * 84;
            const float* usf = sm + OFF_US + 4 * e;
            const float* dts = sm + OFF_DOTS + e * 16;
            const float* mx  = sm + OFF_MIXS + e * MIX_STRIDE;
            float* obase = out + (size_t)rec * 240;
            const float ux = usf[0], uy = usf[1], uz = usf[2];

            #pragma unroll
            for (int it = 0; it < 15; it++) {
                const int gg = 4 * it + sub;
                float4 val;
                if (it < 2) {                 // msg_s: s * gate
                    float4 s4 = *(const float4*)(dst + 4 * gg);
                    float4 m4 = *(const float4*)(mx + 4 * gg);
                    val.x = s4.x*m4.x; val.y = s4.y*m4.y; val.z = s4.z*m4.z; val.w = s4.w*m4.w;
                } else if (it == 2) {         // msg_s: (v.u) * gate
                    float4 d4 = *(const float4*)(dts + 4 * sub);
                    float4 m4 = *(const float4*)(mx + 4 * gg);
                    val.x = d4.x*m4.x; val.y = d4.y*m4.y; val.z = d4.z*m4.z; val.w = d4.w*m4.w;
                } else {                      // msg_v flat regions
                    const int j0 = 16 * it + 4 * sub - 48;
                    const int ch0 = j0 / 3;
                    const int i0 = j0 - 3 * ch0;
                    const float m0 = mx[48 + ch0];
                    const float m1 = mx[48 + ch0 + 1];
                    float tmp[4];
                    if (it < 6) {             // filtered v (ch 0..15)
                        float4 vv = *(const float4*)(dst + 32 + j0);
                        float vvq[4] = {vv.x, vv.y, vv.z, vv.w};
                        #pragma unroll
                        for (int q = 0; q < 4; q++) {
                            bool cross = (i0 + q) >= 3;
                            tmp[q] = vvq[q] * (cross ? m1 : m0);
                        }
                    } else if (it < 12) {     // s x Y1 (ch 16..47)
                        float s0 = dst[ch0 - 16];
                        float s1 = dst[ch0 - 15];
                        #pragma unroll
                        for (int q = 0; q < 4; q++) {
                            bool cross = (i0 + q) >= 3;
                            int i = i0 + q - (cross ? 3 : 0);
                            float u = (i == 0) ? ux : ((i == 1) ? uy : uz);
                            tmp[q] = (cross ? s1 : s0) * u * (cross ? m1 : m0);
                        }
                    } else {                  // v x Y2 (ch 48..63), sqrt1.5 folded in gate
                        int jj = j0 - 144;    // = 3c + i
                        float4 vv = *(const float4*)(dst + 32 + jj);
                        float vvq[4] = {vv.x, vv.y, vv.z, vv.w};
                        float d0 = dts[ch0 - 48];
                        float d1 = (ch0 < 63) ? dts[ch0 - 47] : d0;
                        #pragma unroll
                        for (int q = 0; q < 4; q++) {
                            bool cross = (i0 + q) >= 3;
                            int i = i0 + q - (cross ? 3 : 0);
                            float u = (i == 0) ? ux : ((i == 1) ? uy : uz);
                            float dd = cross ? d1 : d0;
                            tmp[q] = (u * dd - vvq[q] * 0.3333333333333333f) * (cross ? m1 : m0);
                        }
                    }
                    val.x = tmp[0]; val.y = tmp[1]; val.z = tmp[2]; val.w = tmp[3];
                }
                if (ok) {
                    float* addr = obase + 4 * gg;
                    asm volatile("red.global.add.v4.f32 [%0], {%1,%2,%3,%4};"
                                 :: "l"(addr), "f"(val.x), "f"(val.y), "f"(val.z), "f"(val.w)
                                 : "memory");
                }
            }
        }
        __syncthreads();   // smem reused next tile
    }
}

extern "C" void kernel_launch(void* const* d_in, const int* in_sizes, int n_in,
                              void* d_out, int out_size) {
    const float* vectors   = (const float*)d_in[0];
    const float* node_s    = (const float*)d_in[1];
    const float* node_v    = (const float*)d_in[2];
    const float* W0        = (const float*)d_in[3];
    const float* W1        = (const float*)d_in[4];
    const float* W2        = (const float*)d_in[5];
    const int*   senders   = (const int*)d_in[6];
    const int*   receivers = (const int*)d_in[7];
    float*       out       = (float*)d_out;

    int E = in_sizes[6];
    int numTiles = (E + TE - 1) / TE;

    cudaFuncSetAttribute(mp_kernel, cudaFuncAttributeMaxDynamicSharedMemorySize, SMEM_BYTES);

    cudaMemsetAsync(d_out, 0, (size_t)out_size * sizeof(float), 0);

    int grid = 296;                      // persistent: 2 CTAs/SM
    if (grid > numTiles) grid = numTiles;
    mp_kernel<<<grid, THREADS, SMEM_BYTES>>>(vectors, node_s, node_v, W0, W1, W2,
                                             senders, receivers, out, E, numTiles);
}

// round 9
// speedup vs baseline: 2.0387x; 1.1054x over previous
#include <cuda_runtime.h>
#include <cuda_bf16.h>
#include <math.h>
#include <stdint.h>

#define TE 64
#define THREADS 512

// ---- smem layout (32-bit word offsets) ----
#define OFF_W0    0        // fp32 [8][64] folded 1/sqrt(8)               512
#define OFF_B2    512      // packed units [64 n][4 k][4 tq][16B]         4096
#define OFF_B3    4608     // packed units [112 n][4 k][4 tq][16B]        7168
// union region: A-frags + EMBT alias MIXS
#define OFF_AHI   11776    // A hi frag units [4 ms][4 k][8 g][4 tq]      2048
#define OFF_ALO   13824    // A lo                                        2048
#define OFF_EMBT  15872    // fp32 [8][64]                                512
#define OFF_MIXS  11776    // fp32 [64][116] gates (aliases above)        7424
#define OFF_US    19200    // [64][4]                                     256
#define OFF_SVS   19456    // [64][84]                                    5376
#define OFF_DOTS  24832    // [64][16]                                    1024
#define MIX_STRIDE 116
#define SMEM_FLOATS 25856
#define SMEM_BYTES (SMEM_FLOATS * 4)   // 103424 B -> 2 CTAs/SM

__device__ __forceinline__ float swishf(float x) {
    return x * (1.0f / (1.0f + __expf(-x)));
}

__device__ __forceinline__ void split2(float x0, float x1, uint32_t& h, uint32_t& l) {
    __nv_bfloat162 hb = __floats2bfloat162_rn(x0, x1);
    float r0 = x0 - __bfloat162float(hb.x);
    float r1 = x1 - __bfloat162float(hb.y);
    __nv_bfloat162 lb = __floats2bfloat162_rn(r0, r1);
    h = *(uint32_t*)&hb;
    l = *(uint32_t*)&lb;
}

__device__ __forceinline__ void mma_bf16(float* d, uint32_t a0, uint32_t a1,
                                         uint32_t a2, uint32_t a3,
                                         uint32_t b0, uint32_t b1) {
    asm volatile(
        "mma.sync.aligned.m16n8k16.row.col.f32.bf16.bf16.f32 "
        "{%0,%1,%2,%3}, {%4,%5,%6,%7}, {%8,%9}, {%0,%1,%2,%3};"
        : "+f"(d[0]), "+f"(d[1]), "+f"(d[2]), "+f"(d[3])
        : "r"(a0), "r"(a1), "r"(a2), "r"(a3), "r"(b0), "r"(b1));
}

extern "C" __global__ void __launch_bounds__(THREADS, 2)
mp_kernel(const float* __restrict__ vectors,
          const float* __restrict__ node_s,
          const float* __restrict__ node_v,
          const float* __restrict__ W0,
          const float* __restrict__ W1,
          const float* __restrict__ W2,
          const int* __restrict__ senders,
          const int* __restrict__ receivers,
          float* __restrict__ out,
          int E, int numTiles)
{
    extern __shared__ float sm[];
    uint32_t* smw = (uint32_t*)sm;
    const int t = threadIdx.x;

    // ---- one-time weight staging (packed 16B units, swizzled) ----
    for (int i = t; i < 512; i += THREADS) sm[OFF_W0 + i] = W0[i] * 0.35355339059327373f;
    for (int i = t; i < 64 * 32; i += THREADS) {      // B2[n][k] = W1[k][n]/8
        int n = i >> 5, wd = i & 31;
        int k = wd >> 3, r = wd & 7, tq = r & 3, half = r >> 2;
        float x0 = W1[(2*wd)   * 64 + n] * 0.125f;
        float x1 = W1[(2*wd+1) * 64 + n] * 0.125f;
        uint32_t hw, lw;
        split2(x0, x1, hw, lw);
        int kk = (k + n) & 3;
        int base = OFF_B2 + (n * 16 + kk * 4 + tq) * 4;
        smw[base + half] = hw;
        smw[base + 2 + half] = lw;
    }
    for (int i = t; i < 112 * 32; i += THREADS) {     // B3[n][k] = W2[k][n]*scl(n)
        int n = i >> 5, wd = i & 31;
        int k = wd >> 3, r = wd & 7, tq = r & 3, half = r >> 2;
        float scl = (n >= 96) ? 0.03125f * 1.224744871391589f : 0.03125f;
        float x0 = W2[(2*wd)   * 112 + n] * scl;
        float x1 = W2[(2*wd+1) * 112 + n] * scl;
        uint32_t hw, lw;
        split2(x0, x1, hw, lw);
        int kk = (k + n) & 3;
        int base = OFF_B3 + (n * 16 + kk * 4 + tq) * 4;
        smw[base + half] = hw;
        smw[base + 2 + half] = lw;
    }
    __syncthreads();

    const int w = t >> 5, lane = t & 31;
    const int g = lane >> 2, tq = lane & 3;
    const int ms = w >> 2, nq = w & 3;           // 4 M-strips x 4 N-quarters
    const int mb = ms * 16;
    const int aunit0 = (ms * 128 + g * 4 + tq) * 4;   // + k*128 words

    for (int tile = blockIdx.x; tile < numTiles; tile += gridDim.x) {
        const int e0 = tile * TE;

        // ---- stage A: geometry + radial embedding (warps 0-1) ----
        if (t < TE) {
            int e = e0 + t;
            float vx = 0.f, vy = 0.f, vz = 0.f;
            if (e < E) { vx = vectors[3*e+0]; vy = vectors[3*e+1]; vz = vectors[3*e+2]; }
            float r = sqrtf(vx*vx + vy*vy + vz*vz);
            float rinv = (r > 1e-12f) ? 1.0f / r : 0.0f;
            sm[OFF_US + 4*t+0] = vx*rinv; sm[OFF_US + 4*t+1] = vy*rinv;
            sm[OFF_US + 4*t+2] = vz*rinv; sm[OFF_US + 4*t+3] = 0.f;
            float env = 0.0f;
            if (r < 1.0f) {
                float x2 = r*r, x4 = x2*x2, x6 = x4*x2, x7 = x6*r, x8 = x4*x4;
                env = 1.0f - 28.0f*x6 + 48.0f*x7 - 21.0f*x8;
            }
            float pref = (r > 0.0f) ? 1.4142135623730951f * rinv * env : 0.0f;
            float s1, c1;
            sincosf(3.14159265358979323846f * r, &s1, &c1);
            float sn = s1, sp = 0.0f, c2 = 2.0f * c1;
            #pragma unroll
            for (int n = 0; n < 8; n++) {
                sm[OFF_EMBT + n*TE + t] = pref * sn;
                float nx = c2 * sn - sp; sp = sn; sn = nx;
            }
        }
        // gather issue, 8 threads/edge (latency hidden behind stage B)
        const int ge = t >> 3, gsub = t & 7;
        const int geg = e0 + ge;
        const bool gok = (geg < E);
        int snd = gok ? senders[geg] : 0;
        const float4* sp4 = (const float4*)(node_s + (size_t)snd * 32);
        const float4* vp4 = (const float4*)(node_v + (size_t)snd * 48);
        float4 gr[3];
        #pragma unroll
        for (int q = 0; q < 3; q++) {
            int f4i = gsub + 8*q;                 // 0..23, valid < 20
            float4 val = {0.f, 0.f, 0.f, 0.f};
            if (gok && f4i < 20) val = (f4i < 8) ? sp4[f4i] : vp4[f4i - 8];
            gr[q] = val;
        }
        __syncthreads();

        // ---- stage B: GEMM1 (FFMA, K=8) -> packed A fragment unit k=nq ----
        {
            const int nb = nq * 16;
            float acc[2][2][2];
            #pragma unroll
            for (int a = 0; a < 2; a++)
                #pragma unroll
                for (int b = 0; b < 2; b++) { acc[a][b][0] = 0.f; acc[a][b][1] = 0.f; }
            #pragma unroll
            for (int k = 0; k < 8; k++) {
                float e0v = sm[OFF_EMBT + k*TE + mb + g];
                float e1v = sm[OFF_EMBT + k*TE + mb + 8 + g];
                #pragma unroll
                for (int nt = 0; nt < 2; nt++) {
                    float2 wv = *(const float2*)(sm + OFF_W0 + k*64 + nb + nt*8 + 2*tq);
                    acc[0][nt][0] += e0v * wv.x; acc[0][nt][1] += e0v * wv.y;
                    acc[1][nt][0] += e1v * wv.x; acc[1][nt][1] += e1v * wv.y;
                }
            }
            uint32_t h0,l0,h1,l1,h2,l2,h3,l3;
            split2(swishf(acc[0][0][0]), swishf(acc[0][0][1]), h0, l0);
            split2(swishf(acc[1][0][0]), swishf(acc[1][0][1]), h1, l1);
            split2(swishf(acc[0][1][0]), swishf(acc[0][1][1]), h2, l2);
            split2(swishf(acc[1][1][0]), swishf(acc[1][1][1]), h3, l3);
            int au = aunit0 + nq * 128;
            *(uint4*)(smw + OFF_AHI + au) = make_uint4(h0, h1, h2, h3);
            *(uint4*)(smw + OFF_ALO + au) = make_uint4(l0, l1, l2, l3);
        }
        // land gather into smem; compute dots (2 per thread)
        {
            float* dst = sm + OFF_SVS + ge * 84;
            #pragma unroll
            for (int q = 0; q < 3; q++) {
                int f4i = gsub + 8*q;
                if (f4i < 20) *(float4*)(dst + 4 * f4i) = gr[q];
            }
            __syncwarp();
            const float* usf = sm + OFF_US + 4 * ge;
            float ux = usf[0], uy = usf[1], uz = usf[2];
            #pragma unroll
            for (int q = 0; q < 2; q++) {
                int c = 2 * gsub + q;
                const float* vv = dst + 32 + 3 * c;
                sm[OFF_DOTS + ge * 16 + c] = ux*vv[0] + uy*vv[1] + uz*vv[2];
            }
        }
        __syncthreads();

        // ---- stage C: GEMM2 via bf16 mma (3-pass split), M64 N64 K64 ----
        float acc2[2][4];
        {
            const int nb = nq * 16;
            #pragma unroll
            for (int n = 0; n < 2; n++)
                #pragma unroll
                for (int j = 0; j < 4; j++) acc2[n][j] = 0.f;
            #pragma unroll
            for (int k = 0; k < 4; k++) {
                int au = aunit0 + k * 128;
                uint4 ah = *(const uint4*)(smw + OFF_AHI + au);
                uint4 al = *(const uint4*)(smw + OFF_ALO + au);
                #pragma unroll
                for (int n = 0; n < 2; n++) {
                    int row = nb + n*8 + g;
                    int kk = (k + row) & 3;
                    uint4 b = *(const uint4*)(smw + OFF_B2 + (row * 16 + kk * 4 + tq) * 4);
                    mma_bf16(acc2[n], ah.x, ah.y, ah.z, ah.w, b.x, b.y);
                    mma_bf16(acc2[n], ah.x, ah.y, ah.z, ah.w, b.z, b.w);
                    mma_bf16(acc2[n], al.x, al.y, al.z, al.w, b.x, b.y);
                }
            }
        }
        __syncthreads();   // all h1 reads done before overwrite

        // ---- stage D: swish(h2), split -> packed A fragment unit k=nq ----
        {
            uint32_t h0,l0,h1,l1,h2,l2,h3,l3;
            split2(swishf(acc2[0][0]), swishf(acc2[0][1]), h0, l0);
            split2(swishf(acc2[0][2]), swishf(acc2[0][3]), h1, l1);
            split2(swishf(acc2[1][0]), swishf(acc2[1][1]), h2, l2);
            split2(swishf(acc2[1][2]), swishf(acc2[1][3]), h3, l3);
            int au = aunit0 + nq * 128;
            *(uint4*)(smw + OFF_AHI + au) = make_uint4(h0, h1, h2, h3);
            *(uint4*)(smw + OFF_ALO + au) = make_uint4(l0, l1, l2, l3);
        }
        __syncthreads();

        // ---- stage E: GEMM3 via bf16 mma (3-pass split), M64 N112 K64 -> mixs ----
        {
            const int nb3 = (nq < 2) ? 32 * nq : 64 + 24 * (nq - 2);
            const int nt3 = (nq < 2) ? 4 : 3;
            float acc3[4][4];
            #pragma unroll
            for (int n = 0; n < 4; n++)
                #pragma unroll
                for (int j = 0; j < 4; j++) acc3[n][j] = 0.f;
            #pragma unroll
            for (int k = 0; k < 4; k++) {
                int au = aunit0 + k * 128;
                uint4 ah = *(const uint4*)(smw + OFF_AHI + au);
                uint4 al = *(const uint4*)(smw + OFF_ALO + au);
                #pragma unroll
                for (int n = 0; n < 4; n++) {
                    if (n < nt3) {
                        int row = nb3 + n*8 + g;
                        int kk = (k + row) & 3;
                        uint4 b = *(const uint4*)(smw + OFF_B3 + (row * 16 + kk * 4 + tq) * 4);
                        mma_bf16(acc3[n], ah.x, ah.y, ah.z, ah.w, b.x, b.y);
                        mma_bf16(acc3[n], ah.x, ah.y, ah.z, ah.w, b.z, b.w);
                        mma_bf16(acc3[n], al.x, al.y, al.z, al.w, b.x, b.y);
                    }
                }
            }
            __syncthreads();   // A/EMBT fully read before gate store aliases them
            #pragma unroll
            for (int n = 0; n < 4; n++) {
                if (n < nt3) {
                    int col = nb3 + n*8 + 2*tq;
                    *(float2*)(sm + OFF_MIXS + (mb + g) * MIX_STRIDE + col) =
                        make_float2(acc3[n][0], acc3[n][1]);
                    *(float2*)(sm + OFF_MIXS + (mb + g + 8) * MIX_STRIDE + col) =
                        make_float2(acc3[n][2], acc3[n][3]);
                }
            }
        }
        __syncthreads();

        // ---- stage G: message formation + atomic scatter, 8 threads/edge ----
        {
            const int e = t >> 3, sub = t & 7;
            const int eg2 = e0 + e;
            const bool ok = (eg2 < E);
            int rec = ok ? receivers[eg2] : 0;
            const float* dst = sm + OFF_SVS + e * 84;
            const float* usf = sm + OFF_US + 4 * e;
            const float* dts = sm + OFF_DOTS + e * 16;
            const float* mx  = sm + OFF_MIXS + e * MIX_STRIDE;
            float* obase = out + (size_t)rec * 240;
            const float ux = usf[0], uy = usf[1], uz = usf[2];

            #pragma unroll
            for (int it = 0; it < 8; it++) {
                const int gg = 8 * it + sub;              // 0..63, valid < 60
                if (it == 7 && sub >= 4) break;
                float4 val;
                if (gg < 8) {                 // msg_s: s * gate
                    float4 s4 = *(const float4*)(dst + 4 * gg);
                    float4 m4 = *(const float4*)(mx + 4 * gg);
                    val.x = s4.x*m4.x; val.y = s4.y*m4.y; val.z = s4.z*m4.z; val.w = s4.w*m4.w;
                } else if (gg < 12) {         // msg_s: (v.u) * gate
                    float4 d4 = *(const float4*)(dts + 4 * (gg - 8));
                    float4 m4 = *(const float4*)(mx + 4 * gg);
                    val.x = d4.x*m4.x; val.y = d4.y*m4.y; val.z = d4.z*m4.z; val.w = d4.w*m4.w;
                } else {                      // msg_v flat regions
                    const int j0 = 4 * gg - 48;
                    const int ch0 = j0 / 3;
                    const int i0 = j0 - 3 * ch0;
                    const float m0 = mx[48 + ch0];
                    const float m1 = mx[48 + ch0 + 1];
                    float tmp[4];
                    if (gg < 24) {            // filtered v (ch 0..15)
                        float4 vv = *(const float4*)(dst + 32 + j0);
                        float vvq[4] = {vv.x, vv.y, vv.z, vv.w};
                        #pragma unroll
                        for (int q = 0; q < 4; q++) {
                            bool cross = (i0 + q) >= 3;
                            tmp[q] = vvq[q] * (cross ? m1 : m0);
                        }
                    } else if (gg < 48) {     // s x Y1 (ch 16..47)
                        float s0 = dst[ch0 - 16];
                        float s1 = dst[ch0 - 15];
                        #pragma unroll
                        for (int q = 0; q < 4; q++) {
                            bool cross = (i0 + q) >= 3;
                            int i = i0 + q - (cross ? 3 : 0);
                            float u = (i == 0) ? ux : ((i == 1) ? uy : uz);
                            tmp[q] = (cross ? s1 : s0) * u * (cross ? m1 : m0);
                        }
                    } else {                  // v x Y2 (ch 48..63), sqrt1.5 folded in gate
                        int jj = j0 - 144;
                        float4 vv = *(const float4*)(dst + 32 + jj);
                        float vvq[4] = {vv.x, vv.y, vv.z, vv.w};
                        float d0 = dts[ch0 - 48];
                        float d1 = dts[ch0 - 47];
                        #pragma unroll
                        for (int q = 0; q < 4; q++) {
                            bool cross = (i0 + q) >= 3;
                            int i = i0 + q - (cross ? 3 : 0);
                            float u = (i == 0) ? ux : ((i == 1) ? uy : uz);
                            float dd = cross ? d1 : d0;
                            tmp[q] = (u * dd - vvq[q] * 0.3333333333333333f) * (cross ? m1 : m0);
                        }
                    }
                    val.x = tmp[0]; val.y = tmp[1]; val.z = tmp[2]; val.w = tmp[3];
                }
                if (ok) {
                    float* addr = obase + 4 * gg;
                    asm volatile("red.global.add.v4.f32 [%0], {%1,%2,%3,%4};"
                                 :: "l"(addr), "f"(val.x), "f"(val.y), "f"(val.z), "f"(val.w)
                                 : "memory");
                }
            }
        }
        __syncthreads();   // smem reused next tile
    }
}

extern "C" void kernel_launch(void* const* d_in, const int* in_sizes, int n_in,
                              void* d_out, int out_size) {
    const float* vectors   = (const float*)d_in[0];
    const float* node_s    = (const float*)d_in[1];
    const float* node_v    = (const float*)d_in[2];
    const float* W0        = (const float*)d_in[3];
    const float* W1        = (const float*)d_in[4];
    const float* W2        = (const float*)d_in[5];
    const int*   senders   = (const int*)d_in[6];
    const int*   receivers = (const int*)d_in[7];
    float*       out       = (float*)d_out;

    int E = in_sizes[6];
    int numTiles = (E + TE - 1) / TE;

    cudaFuncSetAttribute(mp_kernel, cudaFuncAttributeMaxDynamicSharedMemorySize, SMEM_BYTES);

    cudaMemsetAsync(d_out, 0, (size_t)out_size * sizeof(float), 0);

    int grid = 296;                      // persistent: 2 CTAs/SM, 32 warps/SM
    if (grid > numTiles) grid = numTiles;
    mp_kernel<<<grid, THREADS, SMEM_BYTES>>>(vectors, node_s, node_v, W0, W1, W2,
                                             senders, receivers, out, E, numTiles);
}

// round 10
// speedup vs baseline: 2.0484x; 1.0047x over previous
#include <cuda_runtime.h>
#include <cuda_bf16.h>
#include <math.h>
#include <stdint.h>

#define TE 64
#define THREADS 512

// ---- smem layout (32-bit word offsets) ----
#define OFF_W0    0        // fp32 [8][64] folded 1/sqrt(8)               512
#define OFF_B2    512      // packed units [64 n][4 k][4 tq][16B]         4096
#define OFF_B3    4608     // packed units [112 n][4 k][4 tq][16B]        7168
// union region: A-frags + EMBT alias MIXS
#define OFF_AHI   11776    // A hi frag units [4 ms][4 k][8 g][4 tq]      2048
#define OFF_ALO   13824    // A lo                                        2048
#define OFF_EMBT  15872    // fp32 [8][64]                                512
#define OFF_MIXS  11776    // fp32 [64][116] gates (aliases above)        7424
#define OFF_US    19200    // [64][4]                                     256
#define OFF_SVS   19456    // [64][84]                                    5376
#define OFF_DOTS  24832    // [64][16]                                    1024
#define MIX_STRIDE 116
#define SMEM_FLOATS 25856
#define SMEM_BYTES (SMEM_FLOATS * 4)   // 103424 B -> 2 CTAs/SM

__device__ __forceinline__ float swishf(float x) {
    return x * (1.0f / (1.0f + __expf(-x)));
}

__device__ __forceinline__ void split2(float x0, float x1, uint32_t& h, uint32_t& l) {
    __nv_bfloat162 hb = __floats2bfloat162_rn(x0, x1);
    float r0 = x0 - __bfloat162float(hb.x);
    float r1 = x1 - __bfloat162float(hb.y);
    __nv_bfloat162 lb = __floats2bfloat162_rn(r0, r1);
    h = *(uint32_t*)&hb;
    l = *(uint32_t*)&lb;
}

__device__ __forceinline__ void mma_bf16(float* d, uint32_t a0, uint32_t a1,
                                         uint32_t a2, uint32_t a3,
                                         uint32_t b0, uint32_t b1) {
    asm volatile(
        "mma.sync.aligned.m16n8k16.row.col.f32.bf16.bf16.f32 "
        "{%0,%1,%2,%3}, {%4,%5,%6,%7}, {%8,%9}, {%0,%1,%2,%3};"
        : "+f"(d[0]), "+f"(d[1]), "+f"(d[2]), "+f"(d[3])
        : "r"(a0), "r"(a1), "r"(a2), "r"(a3), "r"(b0), "r"(b1));
}

extern "C" __global__ void __launch_bounds__(THREADS, 2)
mp_kernel(const float* __restrict__ vectors,
          const float* __restrict__ node_s,
          const float* __restrict__ node_v,
          const float* __restrict__ W0,
          const float* __restrict__ W1,
          const float* __restrict__ W2,
          const int* __restrict__ senders,
          const int* __restrict__ receivers,
          float* __restrict__ out,
          int E, int numTiles)
{
    extern __shared__ float sm[];
    uint32_t* smw = (uint32_t*)sm;
    const int t = threadIdx.x;

    // ---- one-time weight staging (packed 16B units, swizzled) ----
    for (int i = t; i < 512; i += THREADS) sm[OFF_W0 + i] = W0[i] * 0.35355339059327373f;
    for (int i = t; i < 64 * 32; i += THREADS) {      // B2[n][k] = W1[k][n]/8
        int n = i >> 5, wd = i & 31;
        int k = wd >> 3, r = wd & 7, tq = r & 3, half = r >> 2;
        float x0 = W1[(2*wd)   * 64 + n] * 0.125f;
        float x1 = W1[(2*wd+1) * 64 + n] * 0.125f;
        uint32_t hw, lw;
        split2(x0, x1, hw, lw);
        int kk = (k + n) & 3;
        int base = OFF_B2 + (n * 16 + kk * 4 + tq) * 4;
        smw[base + half] = hw;
        smw[base + 2 + half] = lw;
    }
    for (int i = t; i < 112 * 32; i += THREADS) {     // B3[n][k] = W2[k][n]*scl(n)
        int n = i >> 5, wd = i & 31;
        int k = wd >> 3, r = wd & 7, tq = r & 3, half = r >> 2;
        float scl = (n >= 96) ? 0.03125f * 1.224744871391589f : 0.03125f;
        float x0 = W2[(2*wd)   * 112 + n] * scl;
        float x1 = W2[(2*wd+1) * 112 + n] * scl;
        uint32_t hw, lw;
        split2(x0, x1, hw, lw);
        int kk = (k + n) & 3;
        int base = OFF_B3 + (n * 16 + kk * 4 + tq) * 4;
        smw[base + half] = hw;
        smw[base + 2 + half] = lw;
    }
    __syncthreads();

    const int w = t >> 5, lane = t & 31;
    const int g = lane >> 2, tq = lane & 3;
    const int ms = w >> 2, nq = w & 3;           // 4 M-strips x 4 N-quarters
    const int mb = ms * 16;
    const int aunit0 = (ms * 128 + g * 4 + tq) * 4;   // + k*128 words

    // thread-constant base pointers (hoisted out of the tile loop)
    const uint32_t* abh = smw + OFF_AHI + aunit0;
    const uint32_t* abl = smw + OFF_ALO + aunit0;
    // GEMM2: rows nb2 + {0,8} + g ; kk = (k + nb2 + g) & 3, n-independent
    const int nb2 = nq * 16;
    const int r2 = (nb2 + g) & 3;
    const uint32_t* bb2 = smw + OFF_B2 + (nb2 + g) * 64 + tq * 4;   // + n*512 + kk*16
    // GEMM3: rows nb3 + n*8 + g ; kk3 = (k + nb3 + g) & 3
    const int nb3 = (nq < 2) ? 32 * nq : 64 + 24 * (nq - 2);
    const int nt3 = (nq < 2) ? 4 : 3;
    const int r3 = (nb3 + g) & 3;
    const uint32_t* bb3 = smw + OFF_B3 + (nb3 + g) * 64 + tq * 4;   // + n*512 + kk*16

    for (int tile = blockIdx.x; tile < numTiles; tile += gridDim.x) {
        const int e0 = tile * TE;

        // ---- stage A: geometry + radial embedding (warps 0-1) ----
        if (t < TE) {
            int e = e0 + t;
            float vx = 0.f, vy = 0.f, vz = 0.f;
            if (e < E) { vx = vectors[3*e+0]; vy = vectors[3*e+1]; vz = vectors[3*e+2]; }
            float r = sqrtf(vx*vx + vy*vy + vz*vz);
            float rinv = (r > 1e-12f) ? 1.0f / r : 0.0f;
            sm[OFF_US + 4*t+0] = vx*rinv; sm[OFF_US + 4*t+1] = vy*rinv;
            sm[OFF_US + 4*t+2] = vz*rinv; sm[OFF_US + 4*t+3] = 0.f;
            float env = 0.0f;
            if (r < 1.0f) {
                float x2 = r*r, x4 = x2*x2, x6 = x4*x2, x7 = x6*r, x8 = x4*x4;
                env = 1.0f - 28.0f*x6 + 48.0f*x7 - 21.0f*x8;
            }
            float pref = (r > 0.0f) ? 1.4142135623730951f * rinv * env : 0.0f;
            float s1, c1;
            sincosf(3.14159265358979323846f * r, &s1, &c1);
            float sn = s1, sp = 0.0f, c2 = 2.0f * c1;
            #pragma unroll
            for (int n = 0; n < 8; n++) {
                sm[OFF_EMBT + n*TE + t] = pref * sn;
                float nx = c2 * sn - sp; sp = sn; sn = nx;
            }
        }
        // gather issue, 8 threads/edge (latency hidden behind stage B)
        const int ge = t >> 3, gsub = t & 7;
        const int geg = e0 + ge;
        const bool gok = (geg < E);
        int snd = gok ? senders[geg] : 0;
        const float4* sp4 = (const float4*)(node_s + (size_t)snd * 32);
        const float4* vp4 = (const float4*)(node_v + (size_t)snd * 48);
        float4 gr[3];
        #pragma unroll
        for (int q = 0; q < 3; q++) {
            int f4i = gsub + 8*q;                 // 0..23, valid < 20
            float4 val = {0.f, 0.f, 0.f, 0.f};
            if (gok && f4i < 20) val = (f4i < 8) ? sp4[f4i] : vp4[f4i - 8];
            gr[q] = val;
        }
        __syncthreads();

        // ---- stage B: GEMM1 (FFMA, K=8) -> packed A fragment unit k=nq ----
        {
            const int nb = nq * 16;
            float acc[2][2][2];
            #pragma unroll
            for (int a = 0; a < 2; a++)
                #pragma unroll
                for (int b = 0; b < 2; b++) { acc[a][b][0] = 0.f; acc[a][b][1] = 0.f; }
            #pragma unroll
            for (int k = 0; k < 8; k++) {
                float e0v = sm[OFF_EMBT + k*TE + mb + g];
                float e1v = sm[OFF_EMBT + k*TE + mb + 8 + g];
                #pragma unroll
                for (int nt = 0; nt < 2; nt++) {
                    float2 wv = *(const float2*)(sm + OFF_W0 + k*64 + nb + nt*8 + 2*tq);
                    acc[0][nt][0] += e0v * wv.x; acc[0][nt][1] += e0v * wv.y;
                    acc[1][nt][0] += e1v * wv.x; acc[1][nt][1] += e1v * wv.y;
                }
            }
            uint32_t h0,l0,h1,l1,h2,l2,h3,l3;
            split2(swishf(acc[0][0][0]), swishf(acc[0][0][1]), h0, l0);
            split2(swishf(acc[1][0][0]), swishf(acc[1][0][1]), h1, l1);
            split2(swishf(acc[0][1][0]), swishf(acc[0][1][1]), h2, l2);
            split2(swishf(acc[1][1][0]), swishf(acc[1][1][1]), h3, l3);
            *(uint4*)(abh + nq * 128) = make_uint4(h0, h1, h2, h3);
            *(uint4*)(abl + nq * 128) = make_uint4(l0, l1, l2, l3);
        }
        // land gather into smem; compute dots (2 per thread)
        {
            float* dst = sm + OFF_SVS + ge * 84;
            #pragma unroll
            for (int q = 0; q < 3; q++) {
                int f4i = gsub + 8*q;
                if (f4i < 20) *(float4*)(dst + 4 * f4i) = gr[q];
            }
            __syncwarp();
            const float* usf = sm + OFF_US + 4 * ge;
            float ux = usf[0], uy = usf[1], uz = usf[2];
            #pragma unroll
            for (int q = 0; q < 2; q++) {
                int c = 2 * gsub + q;
                const float* vv = dst + 32 + 3 * c;
                sm[OFF_DOTS + ge * 16 + c] = ux*vv[0] + uy*vv[1] + uz*vv[2];
            }
        }
        __syncthreads();

        // ---- stage C: GEMM2 via bf16 mma (3-pass split, pass-interleaved) ----
        float acc2[2][4];
        {
            #pragma unroll
            for (int n = 0; n < 2; n++)
                #pragma unroll
                for (int j = 0; j < 4; j++) acc2[n][j] = 0.f;
            #pragma unroll
            for (int k = 0; k < 4; k++) {
                const int kk = (k + r2) & 3;
                uint4 ah = *(const uint4*)(abh + k * 128);
                uint4 al = *(const uint4*)(abl + k * 128);
                uint4 b0 = *(const uint4*)(bb2 + kk * 16);
                uint4 b1 = *(const uint4*)(bb2 + 512 + kk * 16);
                // pass hh
                mma_bf16(acc2[0], ah.x, ah.y, ah.z, ah.w, b0.x, b0.y);
                mma_bf16(acc2[1], ah.x, ah.y, ah.z, ah.w, b1.x, b1.y);
                // pass hl
                mma_bf16(acc2[0], ah.x, ah.y, ah.z, ah.w, b0.z, b0.w);
                mma_bf16(acc2[1], ah.x, ah.y, ah.z, ah.w, b1.z, b1.w);
                // pass lh
                mma_bf16(acc2[0], al.x, al.y, al.z, al.w, b0.x, b0.y);
                mma_bf16(acc2[1], al.x, al.y, al.z, al.w, b1.x, b1.y);
            }
        }
        __syncthreads();   // all h1 reads done before overwrite

        // ---- stage D: swish(h2), split -> packed A fragment unit k=nq ----
        {
            uint32_t h0,l0,h1,l1,h2,l2,h3,l3;
            split2(swishf(acc2[0][0]), swishf(acc2[0][1]), h0, l0);
            split2(swishf(acc2[0][2]), swishf(acc2[0][3]), h1, l1);
            split2(swishf(acc2[1][0]), swishf(acc2[1][1]), h2, l2);
            split2(swishf(acc2[1][2]), swishf(acc2[1][3]), h3, l3);
            *(uint4*)(abh + nq * 128) = make_uint4(h0, h1, h2, h3);
            *(uint4*)(abl + nq * 128) = make_uint4(l0, l1, l2, l3);
        }
        __syncthreads();

        // ---- stage E: GEMM3 via bf16 mma (3-pass split, pass-interleaved) ----
        {
            float acc3[4][4];
            #pragma unroll
            for (int n = 0; n < 4; n++)
                #pragma unroll
                for (int j = 0; j < 4; j++) acc3[n][j] = 0.f;
            #pragma unroll
            for (int k = 0; k < 4; k++) {
                const int kk = (k + r3) & 3;
                uint4 ah = *(const uint4*)(abh + k * 128);
                uint4 al = *(const uint4*)(abl + k * 128);
                uint4 b[4];
                #pragma unroll
                for (int n = 0; n < 4; n++)
                    if (n < nt3) b[n] = *(const uint4*)(bb3 + n * 512 + kk * 16);
                // pass hh
                #pragma unroll
                for (int n = 0; n < 4; n++)
                    if (n < nt3) mma_bf16(acc3[n], ah.x, ah.y, ah.z, ah.w, b[n].x, b[n].y);
                // pass hl
                #pragma unroll
                for (int n = 0; n < 4; n++)
                    if (n < nt3) mma_bf16(acc3[n], ah.x, ah.y, ah.z, ah.w, b[n].z, b[n].w);
                // pass lh
                #pragma unroll
                for (int n = 0; n < 4; n++)
                    if (n < nt3) mma_bf16(acc3[n], al.x, al.y, al.z, al.w, b[n].x, b[n].y);
            }
            __syncthreads();   // A/EMBT fully read before gate store aliases them
            #pragma unroll
            for (int n = 0; n < 4; n++) {
                if (n < nt3) {
                    int col = nb3 + n*8 + 2*tq;
                    *(float2*)(sm + OFF_MIXS + (mb + g) * MIX_STRIDE + col) =
                        make_float2(acc3[n][0], acc3[n][1]);
                    *(float2*)(sm + OFF_MIXS + (mb + g + 8) * MIX_STRIDE + col) =
                        make_float2(acc3[n][2], acc3[n][3]);
                }
            }
        }
        __syncthreads();

        // ---- stage G: message formation + atomic scatter, 8 threads/edge ----
        {
            const int e = t >> 3, sub = t & 7;
            const int eg2 = e0 + e;
            const bool ok = (eg2 < E);
            int rec = ok ? receivers[eg2] : 0;
            const float* dst = sm + OFF_SVS + e * 84;
            const float* usf = sm + OFF_US + 4 * e;
            const float* dts = sm + OFF_DOTS + e * 16;
            const float* mx  = sm + OFF_MIXS + e * MIX_STRIDE;
            float* obase = out + (size_t)rec * 240;
            const float ux = usf[0], uy = usf[1], uz = usf[2];

            #pragma unroll
            for (int it = 0; it < 8; it++) {
                const int gg = 8 * it + sub;              // 0..63, valid < 60
                if (it == 7 && sub >= 4) break;
                float4 val;
                if (gg < 8) {                 // msg_s: s * gate
                    float4 s4 = *(const float4*)(dst + 4 * gg);
                    float4 m4 = *(const float4*)(mx + 4 * gg);
                    val.x = s4.x*m4.x; val.y = s4.y*m4.y; val.z = s4.z*m4.z; val.w = s4.w*m4.w;
                } else if (gg < 12) {         // msg_s: (v.u) * gate
                    float4 d4 = *(const float4*)(dts + 4 * (gg - 8));
                    float4 m4 = *(const float4*)(mx + 4 * gg);
                    val.x = d4.x*m4.x; val.y = d4.y*m4.y; val.z = d4.z*m4.z; val.w = d4.w*m4.w;
                } else {                      // msg_v flat regions
                    const int j0 = 4 * gg - 48;
                    const int ch0 = j0 / 3;
                    const int i0 = j0 - 3 * ch0;
                    const float m0 = mx[48 + ch0];
                    const float m1 = mx[48 + ch0 + 1];
                    float tmp[4];
                    if (gg < 24) {            // filtered v (ch 0..15)
                        float4 vv = *(const float4*)(dst + 32 + j0);
                        float vvq[4] = {vv.x, vv.y, vv.z, vv.w};
                        #pragma unroll
                        for (int q = 0; q < 4; q++) {
                            bool cross = (i0 + q) >= 3;
                            tmp[q] = vvq[q] * (cross ? m1 : m0);
                        }
                    } else if (gg < 48) {     // s x Y1 (ch 16..47)
                        float s0 = dst[ch0 - 16];
                        float s1 = dst[ch0 - 15];
                        #pragma unroll
                        for (int q = 0; q < 4; q++) {
                            bool cross = (i0 + q) >= 3;
                            int i = i0 + q - (cross ? 3 : 0);
                            float u = (i == 0) ? ux : ((i == 1) ? uy : uz);
                            tmp[q] = (cross ? s1 : s0) * u * (cross ? m1 : m0);
                        }
                    } else {                  // v x Y2 (ch 48..63), sqrt1.5 folded in gate
                        int jj = j0 - 144;
                        float4 vv = *(const float4*)(dst + 32 + jj);
                        float vvq[4] = {vv.x, vv.y, vv.z, vv.w};
                        float d0 = dts[ch0 - 48];
                        float d1 = dts[ch0 - 47];
                        #pragma unroll
                        for (int q = 0; q < 4; q++) {
                            bool cross = (i0 + q) >= 3;
                            int i = i0 + q - (cross ? 3 : 0);
                            float u = (i == 0) ? ux : ((i == 1) ? uy : uz);
                            float dd = cross ? d1 : d0;
                            tmp[q] = (u * dd - vvq[q] * 0.3333333333333333f) * (cross ? m1 : m0);
                        }
                    }
                    val.x = tmp[0]; val.y = tmp[1]; val.z = tmp[2]; val.w = tmp[3];
                }
                if (ok) {
                    float* addr = obase + 4 * gg;
                    asm volatile("red.global.add.v4.f32 [%0], {%1,%2,%3,%4};"
                                 :: "l"(addr), "f"(val.x), "f"(val.y), "f"(val.z), "f"(val.w)
                                 : "memory");
                }
            }
        }
        __syncthreads();   // smem reused next tile
    }
}

extern "C" void kernel_launch(void* const* d_in, const int* in_sizes, int n_in,
                              void* d_out, int out_size) {
    const float* vectors   = (const float*)d_in[0];
    const float* node_s    = (const float*)d_in[1];
    const float* node_v    = (const float*)d_in[2];
    const float* W0        = (const float*)d_in[3];
    const float* W1        = (const float*)d_in[4];
    const float* W2        = (const float*)d_in[5];
    const int*   senders   = (const int*)d_in[6];
    const int*   receivers = (const int*)d_in[7];
    float*       out       = (float*)d_out;

    int E = in_sizes[6];
    int numTiles = (E + TE - 1) / TE;

    cudaFuncSetAttribute(mp_kernel, cudaFuncAttributeMaxDynamicSharedMemorySize, SMEM_BYTES);

    cudaMemsetAsync(d_out, 0, (size_t)out_size * sizeof(float), 0);

    int grid = 296;                      // persistent: 2 CTAs/SM, 32 warps/SM
    if (grid > numTiles) grid = numTiles;
    mp_kernel<<<grid, THREADS, SMEM_BYTES>>>(vectors, node_s, node_v, W0, W1, W2,
                                             senders, receivers, out, E, numTiles);
}